// round 3
// baseline (speedup 1.0000x reference)
#include <cuda_runtime.h>
#include <math.h>

// ---------------------------------------------------------------------------
// ModelSimple: conv4d(1->5,k7)+ReLU -> conv4d(5->10,k7)+ReLU -> Linear -> sigmoid
// R1: packed fp32x2 FFMA (FFMA2) to use the full 128 MAC/cyc/SM fp32 datapath.
// ---------------------------------------------------------------------------

#define NB 128

typedef unsigned long long ull;

__device__ float g_h1[NB * 5 * 20736];
__device__ float g_h2[NB * 10 * 1296];

__device__ __forceinline__ ull pk2(float lo, float hi) {
    ull r; asm("mov.b64 %0,{%1,%2};" : "=l"(r) : "f"(lo), "f"(hi)); return r;
}
__device__ __forceinline__ void fma2(ull& d, ull a, ull b) {
    asm("fma.rn.f32x2 %0,%1,%2,%0;" : "+l"(d) : "l"(a), "l"(b));
}
__device__ __forceinline__ void upk2(ull v, float& lo, float& hi) {
    asm("mov.b64 {%0,%1},%2;" : "=f"(lo), "=f"(hi) : "l"(v));
}

// ---------------------------------------------------------------------------
// conv1: one block per (b, oh). 288 threads: tid -> (ow, od, ot-half).
// Accumulator pairs over ot: acc2[oc][j] holds (ot0+j, ot0+j+3).
// Weights staged per-kh into SMEM as duplicated (w,w) 8B pairs, layout [tap][oc].
// ---------------------------------------------------------------------------
__global__ __launch_bounds__(288, 1)
void conv1_kernel(const float* __restrict__ x,
                  const float* __restrict__ w1,
                  const float* __restrict__ b1)
{
    extern __shared__ float sm1[];
    float* xs = sm1;                       // 40824 floats
    ull*   wd = (ull*)(sm1 + 40824);       // 1715 dup-pairs (per-kh slice)

    const int blk = blockIdx.x;
    const int b  = blk / 12;
    const int oh = blk % 12;

    const float* xb = x + (size_t)b * 104976 + (size_t)oh * 5832;
    for (int i = threadIdx.x; i < 40824; i += 288) xs[i] = xb[i];

    const int tid = threadIdx.x;
    const int ow  = tid / 24;          // 0..11
    const int rem = tid % 24;
    const int od  = rem >> 1;          // 0..11
    const int ot0 = (rem & 1) * 6;     // 0 or 6

    ull acc2[5][3];
#pragma unroll
    for (int c = 0; c < 5; c++)
#pragma unroll
        for (int j = 0; j < 3; j++) acc2[c][j] = 0ull;

#pragma unroll 1
    for (int kh = 0; kh < 7; kh++) {
        __syncthreads();   // xs ready (kh=0) / wd reads done (kh>0)
        for (int i = tid; i < 1715; i += 288) {
            const int tap = i / 5;
            const int oc  = i - tap * 5;
            const float v = w1[oc * 2401 + kh * 343 + tap];
            wd[i] = pk2(v, v);
        }
        __syncthreads();

#pragma unroll 1
        for (int kw = 0; kw < 7; kw++) {
#pragma unroll
            for (int kd = 0; kd < 7; kd++) {
                const float* xp = xs + (((kh * 18) + (ow + kw)) * 18 + (od + kd)) * 18 + ot0;
                float xr[12];
#pragma unroll
                for (int i = 0; i < 12; i++) xr[i] = xp[i];
                ull q[9];
#pragma unroll
                for (int i = 0; i < 9; i++) q[i] = pk2(xr[i], xr[i + 3]);

                const ull* wrow = wd + (size_t)((kw * 7 + kd) * 7) * 5;
#pragma unroll
                for (int kt = 0; kt < 7; kt++) {
#pragma unroll
                    for (int oc = 0; oc < 5; oc++) {
                        const ull w = wrow[kt * 5 + oc];
                        fma2(acc2[oc][0], w, q[kt]);
                        fma2(acc2[oc][1], w, q[kt + 1]);
                        fma2(acc2[oc][2], w, q[kt + 2]);
                    }
                }
            }
        }
    }

    // h1 layout: [b][oc][oh][ow][od][ot]
    const size_t obase = (size_t)b * 103680 + (size_t)oh * 1728
                       + (size_t)ow * 144 + (size_t)od * 12 + ot0;
#pragma unroll
    for (int oc = 0; oc < 5; oc++) {
        const float bias = b1[oc];
#pragma unroll
        for (int j = 0; j < 3; j++) {
            float vlo, vhi;
            upk2(acc2[oc][j], vlo, vhi);
            vlo += bias; vhi += bias;
            g_h1[obase + (size_t)oc * 20736 + j]     = vlo > 0.f ? vlo : 0.f;
            g_h1[obase + (size_t)oc * 20736 + j + 3] = vhi > 0.f ? vhi : 0.f;
        }
    }
}

// ---------------------------------------------------------------------------
// conv2: one block per batch. 432 threads: tid -> (oh, ow, od, ot-half of 3).
// Accumulator pairs over oc: acc2[j][t'] holds (oc=2j, oc=2j+1) at ot=ot0+t'.
// Weights staged per (ic, kh) transposed [tap][ocpair] as natural 8B pairs.
// ---------------------------------------------------------------------------
__global__ __launch_bounds__(432, 1)
void conv2_kernel(const float* __restrict__ w2,
                  const float* __restrict__ b2)
{
    extern __shared__ float sm2[];
    float* xs  = sm2;                      // 20736 floats
    ull*   wd2 = (ull*)(sm2 + 20736);      // 1715 pairs (per ic,kh slice)

    const int b   = blockIdx.x;
    const int tid = threadIdx.x;
    const int t2  = tid >> 1;              // 0..215
    const int oh  = t2 / 36;               // 0..5
    const int ow  = (t2 / 6) % 6;          // 0..5
    const int od  = t2 % 6;                // 0..5
    const int ot0 = (tid & 1) * 3;         // 0 or 3

    ull acc2[5][3];
#pragma unroll
    for (int j = 0; j < 5; j++)
#pragma unroll
        for (int t = 0; t < 3; t++) acc2[j][t] = 0ull;

#pragma unroll 1
    for (int ic = 0; ic < 5; ic++) {
        __syncthreads();   // previous iteration's xs reads done
        const float* hb = g_h1 + ((size_t)b * 5 + ic) * 20736;
        for (int i = tid; i < 20736; i += 432) xs[i] = hb[i];

#pragma unroll 1
        for (int kh = 0; kh < 7; kh++) {
            __syncthreads();   // xs staged (kh=0) / wd2 reads done (kh>0)
            for (int i = tid; i < 1715; i += 432) {
                const int tap = i / 5;
                const int j   = i - tap * 5;
                const float vlo = w2[((size_t)(2 * j)     * 5 + ic) * 2401 + kh * 343 + tap];
                const float vhi = w2[((size_t)(2 * j + 1) * 5 + ic) * 2401 + kh * 343 + tap];
                wd2[i] = pk2(vlo, vhi);
            }
            __syncthreads();

#pragma unroll 1
            for (int kw = 0; kw < 7; kw++) {
#pragma unroll
                for (int kd = 0; kd < 7; kd++) {
                    const float* xp = xs + (((oh + kh) * 12 + (ow + kw)) * 12 + (od + kd)) * 12 + ot0;
                    float xr[9];
#pragma unroll
                    for (int i = 0; i < 9; i++) xr[i] = xp[i];
                    ull q[9];
#pragma unroll
                    for (int i = 0; i < 9; i++) q[i] = pk2(xr[i], xr[i]);

                    const ull* wrow = wd2 + (size_t)((kw * 7 + kd) * 7) * 5;
#pragma unroll
                    for (int kt = 0; kt < 7; kt++) {
#pragma unroll
                        for (int j = 0; j < 5; j++) {
                            const ull w = wrow[kt * 5 + j];
                            fma2(acc2[j][0], w, q[kt]);
                            fma2(acc2[j][1], w, q[kt + 1]);
                            fma2(acc2[j][2], w, q[kt + 2]);
                        }
                    }
                }
            }
        }
    }

    // h2 layout: [b][oc][oh][ow][od][ot]
    const size_t obase = (size_t)b * 12960 + (size_t)oh * 216
                       + (size_t)ow * 36 + (size_t)od * 6 + ot0;
#pragma unroll
    for (int j = 0; j < 5; j++) {
        const float blo = b2[2 * j];
        const float bhi = b2[2 * j + 1];
#pragma unroll
        for (int t = 0; t < 3; t++) {
            float vlo, vhi;
            upk2(acc2[j][t], vlo, vhi);
            vlo += blo; vhi += bhi;
            g_h2[obase + (size_t)(2 * j)     * 1296 + t] = vlo > 0.f ? vlo : 0.f;
            g_h2[obase + (size_t)(2 * j + 1) * 1296 + t] = vhi > 0.f ? vhi : 0.f;
        }
    }
}

// ---------------------------------------------------------------------------
// linear + sigmoid: one block per batch row, dot over 12960 + reduce.
// ---------------------------------------------------------------------------
__global__ __launch_bounds__(256)
void linear_kernel(const float* __restrict__ wl,
                   const float* __restrict__ bl,
                   float* __restrict__ out)
{
    const int b = blockIdx.x;
    const float* h = g_h2 + (size_t)b * 12960;
    float s = 0.f;
    for (int i = threadIdx.x; i < 12960; i += 256)
        s = fmaf(h[i], wl[i], s);

    __shared__ float red[8];
#pragma unroll
    for (int o = 16; o; o >>= 1) s += __shfl_xor_sync(0xFFFFFFFFu, s, o);
    if ((threadIdx.x & 31) == 0) red[threadIdx.x >> 5] = s;
    __syncthreads();
    if (threadIdx.x < 32) {
        s = (threadIdx.x < 8) ? red[threadIdx.x] : 0.f;
#pragma unroll
        for (int o = 4; o; o >>= 1) s += __shfl_xor_sync(0xFFFFFFFFu, s, o);
        if (threadIdx.x == 0) {
            const float z = s + bl[0];
            out[b] = 1.f / (1.f + expf(-z));
        }
    }
}

// ---------------------------------------------------------------------------
extern "C" void kernel_launch(void* const* d_in, const int* in_sizes, int n_in,
                              void* d_out, int out_size)
{
    const float* x    = (const float*)d_in[0];
    const float* w1   = (const float*)d_in[1];
    const float* b1   = (const float*)d_in[2];
    const float* w2   = (const float*)d_in[3];
    const float* b2   = (const float*)d_in[4];
    const float* wlin = (const float*)d_in[5];
    const float* blin = (const float*)d_in[6];
    float* out = (float*)d_out;

    const size_t smem1 = 40824u * 4 + 1715u * 8;   // 177016 B
    const size_t smem2 = 20736u * 4 + 1715u * 8;   //  96664 B
    cudaFuncSetAttribute(conv1_kernel, cudaFuncAttributeMaxDynamicSharedMemorySize, (int)smem1);
    cudaFuncSetAttribute(conv2_kernel, cudaFuncAttributeMaxDynamicSharedMemorySize, (int)smem2);

    conv1_kernel<<<NB * 12, 288, smem1>>>(x, w1, b1);
    conv2_kernel<<<NB, 432, smem2>>>(w2, b2);
    linear_kernel<<<NB, 256>>>(wlin, blin, out);
}

// round 4
// speedup vs baseline: 1.0297x; 1.0297x over previous
#include <cuda_runtime.h>
#include <cuda_bf16.h>
typedef unsigned int u32;
#define NB 128

// ---------------------------------------------------------------------------
// Globals (no cudaMalloc allowed)
// ---------------------------------------------------------------------------
__device__ __align__(16) u32   g_xp[NB * 18 * 18 * 360];          // x packed, d-stride 20
__device__ __align__(16) u32   g_h1p[NB * 5 * 12 * 12 * 144];     // conv1 out packed
__device__ float               g_h2[NB * 10 * 1296];
__device__ __align__(16) uint4 g_w1p[22 * 4 * 40];                // B1 fragments
__device__ __align__(16) uint4 g_w2p[108 * 4 * 80];               // B2 fragments

// ---------------------------------------------------------------------------
__device__ __forceinline__ u32 ps(float v) {               // split-pack: hi | lo<<16
    __nv_bfloat16 h = __float2bfloat16(v);
    __nv_bfloat16 l = __float2bfloat16(v - __bfloat162float(h));
    return (u32)__bfloat16_as_ushort(h) | ((u32)__bfloat16_as_ushort(l) << 16);
}
__device__ __forceinline__ void sp2(float v0, float v1, u32& hi, u32& lo) {
    __nv_bfloat16 h0 = __float2bfloat16(v0), h1 = __float2bfloat16(v1);
    __nv_bfloat16 l0 = __float2bfloat16(v0 - __bfloat162float(h0));
    __nv_bfloat16 l1 = __float2bfloat16(v1 - __bfloat162float(h1));
    hi = (u32)__bfloat16_as_ushort(h0) | ((u32)__bfloat16_as_ushort(h1) << 16);
    lo = (u32)__bfloat16_as_ushort(l0) | ((u32)__bfloat16_as_ushort(l1) << 16);
}
__device__ __forceinline__ void mma16816(float* c, const u32* a, u32 b0, u32 b1) {
    asm volatile("mma.sync.aligned.m16n8k16.row.col.f32.bf16.bf16.f32 "
        "{%0,%1,%2,%3},{%4,%5,%6,%7},{%8,%9},{%0,%1,%2,%3};"
        : "+f"(c[0]), "+f"(c[1]), "+f"(c[2]), "+f"(c[3])
        : "r"(a[0]), "r"(a[1]), "r"(a[2]), "r"(a[3]), "r"(b0), "r"(b1));
}
__device__ __forceinline__ void cp16(u32 dst, const void* src) {
    asm volatile("cp.async.cg.shared.global [%0], [%1], 16;" :: "r"(dst), "l"(src));
}
__device__ __forceinline__ void cp_commit() { asm volatile("cp.async.commit_group;"); }
__device__ __forceinline__ void cp_wait0()  { asm volatile("cp.async.wait_group 0;"); }

// ---------------------------------------------------------------------------
// pack kernels
// ---------------------------------------------------------------------------
__global__ void pack_x(const float* __restrict__ x) {
    int i = blockIdx.x * 256 + threadIdx.x;
    if (i >= NB * 324 * 360) return;
    int seg = i / 360, r = i % 360, d = r / 20, t = r % 20;
    g_xp[i] = (t < 18) ? ps(x[(size_t)seg * 324 + d * 18 + t]) : 0u;
}
__global__ void pack_w1(const float* __restrict__ w1) {
    int i = blockIdx.x * 256 + threadIdx.x;
    if (i >= 3520) return;
    int kcti = i / 40, n = i % 40, oc = n >> 3, kt = n & 7;
    int k0 = (kcti >> 2) * 16 + 2 * (kcti & 3);
    float v[4];
#pragma unroll
    for (int j = 0; j < 4; j++) {
        int k = k0 + (j & 1) + (j >> 1) * 8;
        v[j] = (k < 343 && kt < 7) ? w1[oc * 2401 + k * 7 + kt] : 0.f;
    }
    uint4 o; sp2(v[0], v[1], o.x, o.z); sp2(v[2], v[3], o.y, o.w);
    g_w1p[i] = o;
}
__global__ void pack_w2(const float* __restrict__ w2) {
    int i = blockIdx.x * 256 + threadIdx.x;
    if (i >= 34560) return;
    int kcti = i / 80, n = i % 80, oc = n >> 3, kt = n & 7;
    int k0 = (kcti >> 2) * 16 + 2 * (kcti & 3);
    float v[4];
#pragma unroll
    for (int j = 0; j < 4; j++) {
        int k = k0 + (j & 1) + (j >> 1) * 8;
        v[j] = 0.f;
        if (k < 1715 && kt < 7) {
            int ic = k / 343, t3 = k - ic * 343;
            v[j] = w2[(size_t)oc * 12005 + ic * 2401 + t3 * 7 + kt];
        }
    }
    uint4 o; sp2(v[0], v[1], o.x, o.z); sp2(v[2], v[3], o.y, o.w);
    g_w2p[i] = o;
}

// ---------------------------------------------------------------------------
// conv1: CTA=(b, oh, ow-half). 256 thr (8 warps). GEMM M256(216used) x N40 x K352
// per owl (6). SMEM: xs 30240 | zero 320 | ws4 14784 | zs 10752  = 224384 B
// ---------------------------------------------------------------------------
__global__ __launch_bounds__(256, 1)
void conv1_mma(const float* __restrict__ b1)
{
    extern __shared__ u32 sm[];
    u32*   xs  = sm;                          // 30240 (+320 zero pad)
    uint4* ws4 = (uint4*)(sm + 30560);        // 22*4*42 = 3696 uint4
    float* zs  = (float*)(sm + 30560 + 14784);// 256*42 f32

    const int bid = blockIdx.x;
    const int b = bid / 24, r0 = bid % 24, oh = r0 >> 1, ow0 = (r0 & 1) * 6;
    const int tid = threadIdx.x;

    for (int i = tid; i < 3520; i += 256) ws4[(i / 40) * 42 + i % 40] = g_w1p[i];
    for (int i = tid; i < 320; i += 256) xs[30240 + i] = 0u;
    const u32* xb = g_xp + (((size_t)b * 18 + oh) * 18 + ow0) * 360;
    for (int j = tid; j < 7560; j += 256) {
        int seg = j / 90, off = j % 90;
        *(uint4*)&xs[seg * 360 + off * 4] =
            *(const uint4*)(xb + ((size_t)(seg / 12) * 18 + seg % 12) * 360 + off * 4);
    }
    __syncthreads();

    const int lane = tid & 31, wid = tid >> 5, gid = lane >> 2, tig = lane & 3;

    for (int owl = 0; owl < 6; owl++) {
        float acc[2][5][4];
#pragma unroll
        for (int mt = 0; mt < 2; mt++)
#pragma unroll
            for (int nt = 0; nt < 5; nt++)
#pragma unroll
                for (int q = 0; q < 4; q++) acc[mt][nt][q] = 0.f;

        for (int kc = 0; kc < 22; kc++) {
            int xo[4];
#pragma unroll
            for (int q = 0; q < 4; q++) {
                int k = kc * 16 + 2 * tig + (q & 1) + (q >> 1) * 8;
                int kh = k / 49, rm = k - kh * 49, kw = rm / 7, kd = rm - kw * 7;
                xo[q] = (k >= 343) ? 30240 : (kh * 12 + owl + kw) * 360 + kd * 20;
            }
            u32 ahi[2][4], alo[2][4];
#pragma unroll
            for (int mt = 0; mt < 2; mt++) {
                int rA = (2 * wid + mt) * 16 + gid, rB = rA + 8;
                u32 pa = xs[xo[0] + rA], pb = xs[xo[1] + rA];
                u32 pc = xs[xo[0] + rB], pd = xs[xo[1] + rB];
                u32 pe = xs[xo[2] + rA], pf = xs[xo[3] + rA];
                u32 pg = xs[xo[2] + rB], ph = xs[xo[3] + rB];
                ahi[mt][0] = __byte_perm(pa, pb, 0x5410); alo[mt][0] = __byte_perm(pa, pb, 0x7632);
                ahi[mt][1] = __byte_perm(pc, pd, 0x5410); alo[mt][1] = __byte_perm(pc, pd, 0x7632);
                ahi[mt][2] = __byte_perm(pe, pf, 0x5410); alo[mt][2] = __byte_perm(pe, pf, 0x7632);
                ahi[mt][3] = __byte_perm(pg, ph, 0x5410); alo[mt][3] = __byte_perm(pg, ph, 0x7632);
            }
#pragma unroll
            for (int nt = 0; nt < 5; nt++) {
                uint4 wv = ws4[(kc * 4 + tig) * 42 + nt * 8 + gid];
#pragma unroll
                for (int mt = 0; mt < 2; mt++) {
                    mma16816(acc[mt][nt], ahi[mt], wv.x, wv.y);  // hh
                    mma16816(acc[mt][nt], alo[mt], wv.x, wv.y);  // lh
                    mma16816(acc[mt][nt], ahi[mt], wv.z, wv.w);  // hl
                }
            }
        }
#pragma unroll
        for (int mt = 0; mt < 2; mt++) {
            int rA = (2 * wid + mt) * 16 + gid;
#pragma unroll
            for (int nt = 0; nt < 5; nt++) {
                int cb = nt * 8 + 2 * tig;
                zs[rA * 42 + cb] = acc[mt][nt][0];       zs[rA * 42 + cb + 1] = acc[mt][nt][1];
                zs[(rA + 8) * 42 + cb] = acc[mt][nt][2]; zs[(rA + 8) * 42 + cb + 1] = acc[mt][nt][3];
            }
        }
        __syncthreads();
        for (int i = tid; i < 720; i += 256) {
            int oc = i / 144, r2 = i - oc * 144, od = r2 / 12, ot = r2 - od * 12;
            float s = __ldg(&b1[oc]);
#pragma unroll
            for (int kt = 0; kt < 7; kt++)
                s += zs[(od * 20 + ot + kt) * 42 + oc * 8 + kt];
            s = fmaxf(s, 0.f);
            g_h1p[((((size_t)b * 5 + oc) * 12 + oh) * 12 + ow0 + owl) * 144 + od * 12 + ot] = ps(s);
        }
        __syncthreads();
    }
}

// ---------------------------------------------------------------------------
// conv2: CTA=(b, oh, ow). 320 thr (10 warps). GEMM M80(72) x N80 x K1728.
// SMEM: xs 35280 | zero 96 | bq 2624 | zs 6560  = 178240 B
// ---------------------------------------------------------------------------
__global__ __launch_bounds__(320, 1)
void conv2_mma(const float* __restrict__ b2)
{
    extern __shared__ u32 sm2[];
    u32*   xs = sm2;                            // 35280 (+96 zero pad)
    u32*   bq = sm2 + 35376;                    // 2*4*82 uint4 = 2624 u32
    float* zs = (float*)(sm2 + 35376 + 2624);   // 80*82 f32

    const int bid = blockIdx.x;
    const int b = bid / 36, r0 = bid % 36, oh = r0 / 6, ow = r0 % 6;
    const int tid = threadIdx.x;
    const u32 bq_s = (u32)__cvta_generic_to_shared(bq);
    const int tg = tid / 80, nn = tid % 80;

    cp16(bq_s + (u32)(tg * 82 + nn) * 16, &g_w2p[tg * 80 + nn]);   // chunk 0 -> buf 0
    cp_commit();
    if (tid < 96) xs[35280 + tid] = 0u;
    for (int j = tid; j < 8820; j += 320) {
        int seg = j / 36, off = j % 36;
        int ic = seg / 49, r3 = seg - ic * 49, kh = r3 / 7, kw = r3 - kh * 7;
        *(uint4*)&xs[seg * 144 + off * 4] =
            *(const uint4*)(g_h1p + ((((size_t)b * 5 + ic) * 12 + oh + kh) * 12 + ow + kw) * 144 + off * 4);
    }
    cp_wait0();
    __syncthreads();

    const int lane = tid & 31, wid = tid >> 5, gid = lane >> 2, tig = lane & 3;
    const int mg = wid % 5, ng = wid / 5;
    const int rA = mg * 16 + gid, rB = rA + 8;

    float acc[5][4];
#pragma unroll
    for (int nt = 0; nt < 5; nt++)
#pragma unroll
        for (int q = 0; q < 4; q++) acc[nt][q] = 0.f;

    for (int kc = 0; kc < 108; kc++) {
        const int buf = kc & 1;
        if (kc < 107) {
            cp16(bq_s + (u32)((((buf ^ 1) * 4 + tg) * 82 + nn)) * 16,
                 &g_w2p[((kc + 1) * 4 + tg) * 80 + nn]);
            cp_commit();
        }
        int xo[4];
#pragma unroll
        for (int q = 0; q < 4; q++) {
            int k = kc * 16 + 2 * tig + (q & 1) + (q >> 1) * 8;
            int seg = k / 7, kd = k - seg * 7;
            xo[q] = (k >= 1715) ? 35280 : seg * 144 + kd * 12;
        }
        u32 pa = xs[xo[0] + rA], pb = xs[xo[1] + rA];
        u32 pc = xs[xo[0] + rB], pd = xs[xo[1] + rB];
        u32 pe = xs[xo[2] + rA], pf = xs[xo[3] + rA];
        u32 pg = xs[xo[2] + rB], ph = xs[xo[3] + rB];
        u32 ahi[4], alo[4];
        ahi[0] = __byte_perm(pa, pb, 0x5410); alo[0] = __byte_perm(pa, pb, 0x7632);
        ahi[1] = __byte_perm(pc, pd, 0x5410); alo[1] = __byte_perm(pc, pd, 0x7632);
        ahi[2] = __byte_perm(pe, pf, 0x5410); alo[2] = __byte_perm(pe, pf, 0x7632);
        ahi[3] = __byte_perm(pg, ph, 0x5410); alo[3] = __byte_perm(pg, ph, 0x7632);
#pragma unroll
        for (int nt = 0; nt < 5; nt++) {
            uint4 wv = ((const uint4*)bq)[(buf * 4 + tig) * 82 + ng * 40 + nt * 8 + gid];
            mma16816(acc[nt], ahi, wv.x, wv.y);
            mma16816(acc[nt], alo, wv.x, wv.y);
            mma16816(acc[nt], ahi, wv.z, wv.w);
        }
        cp_wait0();
        __syncthreads();
    }

#pragma unroll
    for (int nt = 0; nt < 5; nt++) {
        int cb = ng * 40 + nt * 8 + 2 * tig;
        zs[rA * 82 + cb] = acc[nt][0];  zs[rA * 82 + cb + 1] = acc[nt][1];
        zs[rB * 82 + cb] = acc[nt][2];  zs[rB * 82 + cb + 1] = acc[nt][3];
    }
    __syncthreads();
    for (int i = tid; i < 360; i += 320) {
        int oc = i / 36, r2 = i - oc * 36, od = r2 / 6, ot = r2 - od * 6;
        float s = __ldg(&b2[oc]);
#pragma unroll
        for (int kt = 0; kt < 7; kt++)
            s += zs[(od * 12 + ot + kt) * 82 + oc * 8 + kt];
        s = fmaxf(s, 0.f);
        g_h2[(size_t)b * 12960 + oc * 1296 + oh * 216 + ow * 36 + od * 6 + ot] = s;
    }
}

// ---------------------------------------------------------------------------
__global__ __launch_bounds__(256)
void linear_kernel(const float* __restrict__ wl, const float* __restrict__ bl,
                   float* __restrict__ out)
{
    const int b = blockIdx.x;
    const float* h = g_h2 + (size_t)b * 12960;
    float s = 0.f;
    for (int i = threadIdx.x; i < 12960; i += 256) s = fmaf(h[i], wl[i], s);
    __shared__ float red[8];
#pragma unroll
    for (int o = 16; o; o >>= 1) s += __shfl_xor_sync(0xFFFFFFFFu, s, o);
    if ((threadIdx.x & 31) == 0) red[threadIdx.x >> 5] = s;
    __syncthreads();
    if (threadIdx.x < 32) {
        s = (threadIdx.x < 8) ? red[threadIdx.x] : 0.f;
#pragma unroll
        for (int o = 4; o; o >>= 1) s += __shfl_xor_sync(0xFFFFFFFFu, s, o);
        if (threadIdx.x == 0) out[b] = 1.f / (1.f + expf(-(s + bl[0])));
    }
}

// ---------------------------------------------------------------------------
extern "C" void kernel_launch(void* const* d_in, const int* in_sizes, int n_in,
                              void* d_out, int out_size)
{
    const float* x    = (const float*)d_in[0];
    const float* w1   = (const float*)d_in[1];
    const float* b1   = (const float*)d_in[2];
    const float* w2   = (const float*)d_in[3];
    const float* b2   = (const float*)d_in[4];
    const float* wlin = (const float*)d_in[5];
    const float* blin = (const float*)d_in[6];
    float* out = (float*)d_out;

    const size_t smem1 = (30560 + 14784 + 10752) * 4;   // 224384 B
    const size_t smem2 = (35376 + 2624 + 6560) * 4;     // 178240 B
    cudaFuncSetAttribute(conv1_mma, cudaFuncAttributeMaxDynamicSharedMemorySize, (int)smem1);
    cudaFuncSetAttribute(conv2_mma, cudaFuncAttributeMaxDynamicSharedMemorySize, (int)smem2);

    pack_x<<<(NB * 324 * 360 + 255) / 256, 256>>>(x);
    pack_w1<<<14, 256>>>(w1);
    pack_w2<<<135, 256>>>(w2);
    conv1_mma<<<NB * 24, 256, smem1>>>(b1);
    conv2_mma<<<NB * 36, 320, smem2>>>(b2);
    linear_kernel<<<NB, 256>>>(wlin, blin, out);
}

// round 5
// speedup vs baseline: 1.0791x; 1.0480x over previous
#include <cuda_runtime.h>
#include <cuda_bf16.h>
typedef unsigned int u32;
#define NB 128

// ---------------------------------------------------------------------------
// Globals (no cudaMalloc allowed)
// ---------------------------------------------------------------------------
__device__ __align__(16) u32   g_xp[NB * 18 * 18 * 360];          // x packed, d-stride 20
__device__ __align__(16) u32   g_h1p[NB * 5 * 12 * 12 * 144];     // conv1 out packed
__device__ float               g_h2[NB * 10 * 1296];
__device__ __align__(16) uint4 g_w1p[22 * 4 * 40];                // B1 fragments
__device__ __align__(16) uint4 g_w2p[108 * 4 * 80];               // B2 fragments

// ---------------------------------------------------------------------------
__device__ __forceinline__ u32 ps(float v) {               // split-pack: hi | lo<<16
    __nv_bfloat16 h = __float2bfloat16(v);
    __nv_bfloat16 l = __float2bfloat16(v - __bfloat162float(h));
    return (u32)__bfloat16_as_ushort(h) | ((u32)__bfloat16_as_ushort(l) << 16);
}
__device__ __forceinline__ void sp2(float v0, float v1, u32& hi, u32& lo) {
    __nv_bfloat16 h0 = __float2bfloat16(v0), h1 = __float2bfloat16(v1);
    __nv_bfloat16 l0 = __float2bfloat16(v0 - __bfloat162float(h0));
    __nv_bfloat16 l1 = __float2bfloat16(v1 - __bfloat162float(h1));
    hi = (u32)__bfloat16_as_ushort(h0) | ((u32)__bfloat16_as_ushort(h1) << 16);
    lo = (u32)__bfloat16_as_ushort(l0) | ((u32)__bfloat16_as_ushort(l1) << 16);
}
__device__ __forceinline__ void mma16816(float* c, const u32* a, u32 b0, u32 b1) {
    asm volatile("mma.sync.aligned.m16n8k16.row.col.f32.bf16.bf16.f32 "
        "{%0,%1,%2,%3},{%4,%5,%6,%7},{%8,%9},{%0,%1,%2,%3};"
        : "+f"(c[0]), "+f"(c[1]), "+f"(c[2]), "+f"(c[3])
        : "r"(a[0]), "r"(a[1]), "r"(a[2]), "r"(a[3]), "r"(b0), "r"(b1));
}
__device__ __forceinline__ void cp16(u32 dst, const void* src) {
    asm volatile("cp.async.cg.shared.global [%0], [%1], 16;" :: "r"(dst), "l"(src));
}
__device__ __forceinline__ void cp_commit() { asm volatile("cp.async.commit_group;"); }
__device__ __forceinline__ void cp_wait0()  { asm volatile("cp.async.wait_group 0;"); }
__device__ __forceinline__ void cp_wait1()  { asm volatile("cp.async.wait_group 1;"); }

// ---------------------------------------------------------------------------
// pack kernels
// ---------------------------------------------------------------------------
__global__ void pack_x(const float* __restrict__ x) {
    int i = blockIdx.x * 256 + threadIdx.x;
    if (i >= NB * 324 * 360) return;
    int seg = i / 360, r = i % 360, d = r / 20, t = r % 20;
    g_xp[i] = (t < 18) ? ps(x[(size_t)seg * 324 + d * 18 + t]) : 0u;
}
__global__ void pack_w1(const float* __restrict__ w1) {
    int i = blockIdx.x * 256 + threadIdx.x;
    if (i >= 3520) return;
    int kcti = i / 40, n = i % 40, oc = n >> 3, kt = n & 7;
    int k0 = (kcti >> 2) * 16 + 2 * (kcti & 3);
    float v[4];
#pragma unroll
    for (int j = 0; j < 4; j++) {
        int k = k0 + (j & 1) + (j >> 1) * 8;
        v[j] = (k < 343 && kt < 7) ? w1[oc * 2401 + k * 7 + kt] : 0.f;
    }
    uint4 o; sp2(v[0], v[1], o.x, o.z); sp2(v[2], v[3], o.y, o.w);
    g_w1p[i] = o;
}
__global__ void pack_w2(const float* __restrict__ w2) {
    int i = blockIdx.x * 256 + threadIdx.x;
    if (i >= 34560) return;
    int kcti = i / 80, n = i % 80, oc = n >> 3, kt = n & 7;
    int k0 = (kcti >> 2) * 16 + 2 * (kcti & 3);
    float v[4];
#pragma unroll
    for (int j = 0; j < 4; j++) {
        int k = k0 + (j & 1) + (j >> 1) * 8;
        v[j] = 0.f;
        if (k < 1715 && kt < 7) {
            int ic = k / 343, t3 = k - ic * 343;
            v[j] = w2[(size_t)oc * 12005 + ic * 2401 + t3 * 7 + kt];
        }
    }
    uint4 o; sp2(v[0], v[1], o.x, o.z); sp2(v[2], v[3], o.y, o.w);
    g_w2p[i] = o;
}

// ---------------------------------------------------------------------------
// conv1: CTA=(b, oh, ow-half). 512 thr (16 warps, 1 m-tile each).
// GEMM M256(216) x N40 x K352 per owl (6).
// SMEM: xs 30240 | zero 320 | ws4 14784 | zs 10752  = 224384 B
// ---------------------------------------------------------------------------
__global__ __launch_bounds__(512, 1)
void conv1_mma(const float* __restrict__ b1)
{
    extern __shared__ u32 sm[];
    u32*   xs  = sm;                          // 30240 (+320 zero pad)
    uint4* ws4 = (uint4*)(sm + 30560);        // 22*4*42 = 3696 uint4
    float* zs  = (float*)(sm + 30560 + 14784);// 256*42 f32

    const int bid = blockIdx.x;
    const int b = bid / 24, r0 = bid % 24, oh = r0 >> 1, ow0 = (r0 & 1) * 6;
    const int tid = threadIdx.x;

    for (int i = tid; i < 3520; i += 512) ws4[(i / 40) * 42 + i % 40] = g_w1p[i];
    for (int i = tid; i < 320; i += 512) xs[30240 + i] = 0u;
    const u32* xb = g_xp + (((size_t)b * 18 + oh) * 18 + ow0) * 360;
    for (int j = tid; j < 7560; j += 512) {
        int seg = j / 90, off = j % 90;
        *(uint4*)&xs[seg * 360 + off * 4] =
            *(const uint4*)(xb + ((size_t)(seg / 12) * 18 + seg % 12) * 360 + off * 4);
    }
    __syncthreads();

    const int lane = tid & 31, wid = tid >> 5, gid = lane >> 2, tig = lane & 3;
    const int rA = wid * 16 + gid, rB = rA + 8;

    for (int owl = 0; owl < 6; owl++) {
        float acc[5][4];
#pragma unroll
        for (int nt = 0; nt < 5; nt++)
#pragma unroll
            for (int q = 0; q < 4; q++) acc[nt][q] = 0.f;

        for (int kc = 0; kc < 22; kc++) {
            int xo[4];
#pragma unroll
            for (int q = 0; q < 4; q++) {
                int k = kc * 16 + 2 * tig + (q & 1) + (q >> 1) * 8;
                int kh = k / 49, rm = k - kh * 49, kw = rm / 7, kd = rm - kw * 7;
                xo[q] = (k >= 343) ? 30240 : (kh * 12 + owl + kw) * 360 + kd * 20;
            }
            u32 pa = xs[xo[0] + rA], pb = xs[xo[1] + rA];
            u32 pc = xs[xo[0] + rB], pd = xs[xo[1] + rB];
            u32 pe = xs[xo[2] + rA], pf = xs[xo[3] + rA];
            u32 pg = xs[xo[2] + rB], ph = xs[xo[3] + rB];
            u32 ahi[4], alo[4];
            ahi[0] = __byte_perm(pa, pb, 0x5410); alo[0] = __byte_perm(pa, pb, 0x7632);
            ahi[1] = __byte_perm(pc, pd, 0x5410); alo[1] = __byte_perm(pc, pd, 0x7632);
            ahi[2] = __byte_perm(pe, pf, 0x5410); alo[2] = __byte_perm(pe, pf, 0x7632);
            ahi[3] = __byte_perm(pg, ph, 0x5410); alo[3] = __byte_perm(pg, ph, 0x7632);
#pragma unroll
            for (int nt = 0; nt < 5; nt++) {
                uint4 wv = ws4[(kc * 4 + tig) * 42 + nt * 8 + gid];
                mma16816(acc[nt], ahi, wv.x, wv.y);  // hh
                mma16816(acc[nt], alo, wv.x, wv.y);  // lh
                mma16816(acc[nt], ahi, wv.z, wv.w);  // hl
            }
        }
#pragma unroll
        for (int nt = 0; nt < 5; nt++) {
            int cb = nt * 8 + 2 * tig;
            zs[rA * 42 + cb] = acc[nt][0];  zs[rA * 42 + cb + 1] = acc[nt][1];
            zs[rB * 42 + cb] = acc[nt][2];  zs[rB * 42 + cb + 1] = acc[nt][3];
        }
        __syncthreads();
        for (int i = tid; i < 720; i += 512) {
            int oc = i / 144, r2 = i - oc * 144, od = r2 / 12, ot = r2 - od * 12;
            float s = __ldg(&b1[oc]);
#pragma unroll
            for (int kt = 0; kt < 7; kt++)
                s += zs[(od * 20 + ot + kt) * 42 + oc * 8 + kt];
            s = fmaxf(s, 0.f);
            g_h1p[((((size_t)b * 5 + oc) * 12 + oh) * 12 + ow0 + owl) * 144 + od * 12 + ot] = ps(s);
        }
        __syncthreads();
    }
}

// ---------------------------------------------------------------------------
// conv2: CTA=(b, oh, ow). 320 thr (10 warps). GEMM M80(72) x N80 x K1728.
// B staged in 4-kc chunks (27 chunks), double-buffered cp.async,
// 2 barriers per chunk instead of per-kc sync.
// SMEM: xs 35280 | zero 96 | bq 2*16*82 uint4 = 10496 u32 | zs 6560  = 209728 B
// ---------------------------------------------------------------------------
__global__ __launch_bounds__(320, 1)
void conv2_mma(const float* __restrict__ b2)
{
    extern __shared__ u32 sm2[];
    u32*   xs = sm2;                             // 35280 (+96 zero pad)
    uint4* bq = (uint4*)(sm2 + 35376);           // 2 * 16 * 82 uint4
    float* zs = (float*)(sm2 + 35376 + 10496);   // 80*82 f32

    const int bid = blockIdx.x;
    const int b = bid / 36, r0 = bid % 36, oh = r0 / 6, ow = r0 % 6;
    const int tid = threadIdx.x;
    const u32 bq_s = (u32)__cvta_generic_to_shared(bq);

    // prologue: issue chunk 0 -> buf 0 (16 kcti-rows x 80 cols)
#pragma unroll
    for (int s = 0; s < 4; s++) {
        int j = tid + s * 320;           // 0..1279
        int r = j / 80, c = j % 80;
        cp16(bq_s + (u32)(r * 82 + c) * 16, &g_w2p[r * 80 + c]);
    }
    cp_commit();

    if (tid < 96) xs[35280 + tid] = 0u;
    for (int j = tid; j < 8820; j += 320) {
        int seg = j / 36, off = j % 36;
        int ic = seg / 49, r3 = seg - ic * 49, kh = r3 / 7, kw = r3 - kh * 7;
        *(uint4*)&xs[seg * 144 + off * 4] =
            *(const uint4*)(g_h1p + ((((size_t)b * 5 + ic) * 12 + oh + kh) * 12 + ow + kw) * 144 + off * 4);
    }

    const int lane = tid & 31, wid = tid >> 5, gid = lane >> 2, tig = lane & 3;
    const int mg = wid % 5, ng = wid / 5;
    const int rA = mg * 16 + gid, rB = rA + 8;

    float acc[5][4];
#pragma unroll
    for (int nt = 0; nt < 5; nt++)
#pragma unroll
        for (int q = 0; q < 4; q++) acc[nt][q] = 0.f;

    for (int ch = 0; ch < 27; ch++) {
        const int buf = ch & 1;
        if (ch < 26) {   // prefetch next chunk into other buffer
            const int base = (ch + 1) * 16;
#pragma unroll
            for (int s = 0; s < 4; s++) {
                int j = tid + s * 320;
                int r = j / 80, c = j % 80;
                cp16(bq_s + (u32)(((buf ^ 1) * 16 + r) * 82 + c) * 16,
                     &g_w2p[(base + r) * 80 + c]);
            }
            cp_commit();
            cp_wait1();
        } else {
            cp_wait0();
        }
        __syncthreads();   // chunk ch visible to all warps

#pragma unroll 1
        for (int kk = 0; kk < 4; kk++) {
            const int kc = ch * 4 + kk;
            int xo[4];
#pragma unroll
            for (int q = 0; q < 4; q++) {
                int k = kc * 16 + 2 * tig + (q & 1) + (q >> 1) * 8;
                int seg = k / 7, kd = k - seg * 7;
                xo[q] = (k >= 1715) ? 35280 : seg * 144 + kd * 12;
            }
            u32 pa = xs[xo[0] + rA], pb = xs[xo[1] + rA];
            u32 pc = xs[xo[0] + rB], pd = xs[xo[1] + rB];
            u32 pe = xs[xo[2] + rA], pf = xs[xo[3] + rA];
            u32 pg = xs[xo[2] + rB], ph = xs[xo[3] + rB];
            u32 ahi[4], alo[4];
            ahi[0] = __byte_perm(pa, pb, 0x5410); alo[0] = __byte_perm(pa, pb, 0x7632);
            ahi[1] = __byte_perm(pc, pd, 0x5410); alo[1] = __byte_perm(pc, pd, 0x7632);
            ahi[2] = __byte_perm(pe, pf, 0x5410); alo[2] = __byte_perm(pe, pf, 0x7632);
            ahi[3] = __byte_perm(pg, ph, 0x5410); alo[3] = __byte_perm(pg, ph, 0x7632);
#pragma unroll
            for (int nt = 0; nt < 5; nt++) {
                uint4 wv = bq[(buf * 16 + kk * 4 + tig) * 82 + ng * 40 + nt * 8 + gid];
                mma16816(acc[nt], ahi, wv.x, wv.y);
                mma16816(acc[nt], alo, wv.x, wv.y);
                mma16816(acc[nt], ahi, wv.z, wv.w);
            }
        }
        __syncthreads();   // reads of buf done before it is refilled
    }

#pragma unroll
    for (int nt = 0; nt < 5; nt++) {
        int cb = ng * 40 + nt * 8 + 2 * tig;
        zs[rA * 82 + cb] = acc[nt][0];  zs[rA * 82 + cb + 1] = acc[nt][1];
        zs[rB * 82 + cb] = acc[nt][2];  zs[rB * 82 + cb + 1] = acc[nt][3];
    }
    __syncthreads();
    for (int i = tid; i < 360; i += 320) {
        int oc = i / 36, r2 = i - oc * 36, od = r2 / 6, ot = r2 - od * 6;
        float s = __ldg(&b2[oc]);
#pragma unroll
        for (int kt = 0; kt < 7; kt++)
            s += zs[(od * 12 + ot + kt) * 82 + oc * 8 + kt];
        s = fmaxf(s, 0.f);
        g_h2[(size_t)b * 12960 + oc * 1296 + oh * 216 + ow * 36 + od * 6 + ot] = s;
    }
}

// ---------------------------------------------------------------------------
__global__ __launch_bounds__(256)
void linear_kernel(const float* __restrict__ wl, const float* __restrict__ bl,
                   float* __restrict__ out)
{
    const int b = blockIdx.x;
    const float* h = g_h2 + (size_t)b * 12960;
    float s = 0.f;
    for (int i = threadIdx.x; i < 12960; i += 256) s = fmaf(h[i], wl[i], s);
    __shared__ float red[8];
#pragma unroll
    for (int o = 16; o; o >>= 1) s += __shfl_xor_sync(0xFFFFFFFFu, s, o);
    if ((threadIdx.x & 31) == 0) red[threadIdx.x >> 5] = s;
    __syncthreads();
    if (threadIdx.x < 32) {
        s = (threadIdx.x < 8) ? red[threadIdx.x] : 0.f;
#pragma unroll
        for (int o = 4; o; o >>= 1) s += __shfl_xor_sync(0xFFFFFFFFu, s, o);
        if (threadIdx.x == 0) out[b] = 1.f / (1.f + expf(-(s + bl[0])));
    }
}

// ---------------------------------------------------------------------------
extern "C" void kernel_launch(void* const* d_in, const int* in_sizes, int n_in,
                              void* d_out, int out_size)
{
    const float* x    = (const float*)d_in[0];
    const float* w1   = (const float*)d_in[1];
    const float* b1   = (const float*)d_in[2];
    const float* w2   = (const float*)d_in[3];
    const float* b2   = (const float*)d_in[4];
    const float* wlin = (const float*)d_in[5];
    const float* blin = (const float*)d_in[6];
    float* out = (float*)d_out;

    const size_t smem1 = (30560 + 14784 + 10752) * 4;    // 224384 B
    const size_t smem2 = (35376 + 10496 + 6560) * 4;     // 209728 B
    cudaFuncSetAttribute(conv1_mma, cudaFuncAttributeMaxDynamicSharedMemorySize, (int)smem1);
    cudaFuncSetAttribute(conv2_mma, cudaFuncAttributeMaxDynamicSharedMemorySize, (int)smem2);

    pack_x<<<(NB * 324 * 360 + 255) / 256, 256>>>(x);
    pack_w1<<<14, 256>>>(w1);
    pack_w2<<<135, 256>>>(w2);
    conv1_mma<<<NB * 24, 512, smem1>>>(b1);
    conv2_mma<<<NB * 36, 320, smem2>>>(b2);
    linear_kernel<<<NB, 256>>>(wlin, blin, out);
}

// round 6
// speedup vs baseline: 1.2303x; 1.1401x over previous
#include <cuda_runtime.h>
#include <cuda_fp16.h>
typedef unsigned int u32;
#define NB 128

// ---------------------------------------------------------------------------
// Globals (no cudaMalloc allowed)
// ---------------------------------------------------------------------------
__device__ __align__(16) u32   g_xp[NB * 18 * 18 * 360];          // x split-packed fp16, d-stride 20
__device__ __align__(16) u32   g_h1p[NB * 5 * 12 * 12 * 144];     // conv1 out split-packed fp16
__device__ float               g_h2[NB * 10 * 1296];
__device__ __align__(16) uint2 g_w1p[22 * 4 * 40];                // B1 fp16 fragments
__device__ __align__(16) uint2 g_w2p[108 * 4 * 80];               // B2 fp16 fragments

// ---------------------------------------------------------------------------
__device__ __forceinline__ u32 psh(float v) {   // split-pack: fp16 hi | fp16 lo<<16
    __half h = __float2half_rn(v);
    __half l = __float2half_rn(v - __half2float(h));
    return (u32)__half_as_ushort(h) | ((u32)__half_as_ushort(l) << 16);
}
__device__ __forceinline__ u32 ph2(float v0, float v1) {   // two fp16 values packed
    return (u32)__half_as_ushort(__float2half_rn(v0))
         | ((u32)__half_as_ushort(__float2half_rn(v1)) << 16);
}
__device__ __forceinline__ void mma16816(float* c, const u32* a, u32 b0, u32 b1) {
    asm volatile("mma.sync.aligned.m16n8k16.row.col.f32.f16.f16.f32 "
        "{%0,%1,%2,%3},{%4,%5,%6,%7},{%8,%9},{%0,%1,%2,%3};"
        : "+f"(c[0]), "+f"(c[1]), "+f"(c[2]), "+f"(c[3])
        : "r"(a[0]), "r"(a[1]), "r"(a[2]), "r"(a[3]), "r"(b0), "r"(b1));
}
__device__ __forceinline__ void cp16(u32 dst, const void* src) {
    asm volatile("cp.async.cg.shared.global [%0], [%1], 16;" :: "r"(dst), "l"(src));
}
__device__ __forceinline__ void cp_commit() { asm volatile("cp.async.commit_group;"); }
__device__ __forceinline__ void cp_wait0()  { asm volatile("cp.async.wait_group 0;"); }
__device__ __forceinline__ void cp_wait1()  { asm volatile("cp.async.wait_group 1;"); }

// ---------------------------------------------------------------------------
// pack kernels
// ---------------------------------------------------------------------------
__global__ void pack_x(const float* __restrict__ x) {
    int i = blockIdx.x * 256 + threadIdx.x;
    if (i >= NB * 324 * 360) return;
    int seg = i / 360, r = i % 360, d = r / 20, t = r % 20;
    g_xp[i] = (t < 18) ? psh(x[(size_t)seg * 324 + d * 18 + t]) : 0u;
}
__global__ void pack_w1(const float* __restrict__ w1) {
    int i = blockIdx.x * 256 + threadIdx.x;
    if (i >= 3520) return;
    int kcti = i / 40, n = i % 40, oc = n >> 3, kt = n & 7;
    int k0 = (kcti >> 2) * 16 + 2 * (kcti & 3);
    float v[4];
#pragma unroll
    for (int j = 0; j < 4; j++) {
        int k = k0 + (j & 1) + (j >> 1) * 8;
        v[j] = (k < 343 && kt < 7) ? w1[oc * 2401 + k * 7 + kt] : 0.f;
    }
    uint2 o; o.x = ph2(v[0], v[1]); o.y = ph2(v[2], v[3]);
    g_w1p[i] = o;
}
__global__ void pack_w2(const float* __restrict__ w2) {
    int i = blockIdx.x * 256 + threadIdx.x;
    if (i >= 34560) return;
    int kcti = i / 80, n = i % 80, oc = n >> 3, kt = n & 7;
    int k0 = (kcti >> 2) * 16 + 2 * (kcti & 3);
    float v[4];
#pragma unroll
    for (int j = 0; j < 4; j++) {
        int k = k0 + (j & 1) + (j >> 1) * 8;
        v[j] = 0.f;
        if (k < 1715 && kt < 7) {
            int ic = k / 343, t3 = k - ic * 343;
            v[j] = w2[(size_t)oc * 12005 + ic * 2401 + t3 * 7 + kt];
        }
    }
    uint2 o; o.x = ph2(v[0], v[1]); o.y = ph2(v[2], v[3]);
    g_w2p[i] = o;
}

// ---------------------------------------------------------------------------
// conv1: CTA=(b, oh, ow-half). 512 thr (16 warps, 1 m-tile each).
// GEMM M256(216) x N40 x K352 per owl (6). 2-term fp16: Z = ahi*B + alo*B.
// SMEM: xs 30240 | zero 320 | ws2 7392 | zs 10752  = 194816 B
// ---------------------------------------------------------------------------
__global__ __launch_bounds__(512, 1)
void conv1_mma(const float* __restrict__ b1)
{
    extern __shared__ u32 sm[];
    u32*   xs  = sm;                          // 30240 (+320 zero pad)
    uint2* ws2 = (uint2*)(sm + 30560);        // 22*4*42 = 3696 uint2
    float* zs  = (float*)(sm + 30560 + 7392); // 256*42 f32

    const int bid = blockIdx.x;
    const int b = bid / 24, r0 = bid % 24, oh = r0 >> 1, ow0 = (r0 & 1) * 6;
    const int tid = threadIdx.x;

    for (int i = tid; i < 3520; i += 512) ws2[(i / 40) * 42 + i % 40] = g_w1p[i];
    for (int i = tid; i < 320; i += 512) xs[30240 + i] = 0u;
    const u32* xb = g_xp + (((size_t)b * 18 + oh) * 18 + ow0) * 360;
    for (int j = tid; j < 7560; j += 512) {
        int seg = j / 90, off = j % 90;
        *(uint4*)&xs[seg * 360 + off * 4] =
            *(const uint4*)(xb + ((size_t)(seg / 12) * 18 + seg % 12) * 360 + off * 4);
    }
    __syncthreads();

    const int lane = tid & 31, wid = tid >> 5, gid = lane >> 2, tig = lane & 3;
    const int rA = wid * 16 + gid, rB = rA + 8;

    for (int owl = 0; owl < 6; owl++) {
        float acc[5][4];
#pragma unroll
        for (int nt = 0; nt < 5; nt++)
#pragma unroll
            for (int q = 0; q < 4; q++) acc[nt][q] = 0.f;

        for (int kc = 0; kc < 22; kc++) {
            int xo[4];
#pragma unroll
            for (int q = 0; q < 4; q++) {
                int k = kc * 16 + 2 * tig + (q & 1) + (q >> 1) * 8;
                int kh = k / 49, rm = k - kh * 49, kw = rm / 7, kd = rm - kw * 7;
                xo[q] = (k >= 343) ? 30240 : (kh * 12 + owl + kw) * 360 + kd * 20;
            }
            u32 pa = xs[xo[0] + rA], pb = xs[xo[1] + rA];
            u32 pc = xs[xo[0] + rB], pd = xs[xo[1] + rB];
            u32 pe = xs[xo[2] + rA], pf = xs[xo[3] + rA];
            u32 pg = xs[xo[2] + rB], ph = xs[xo[3] + rB];
            u32 ahi[4], alo[4];
            ahi[0] = __byte_perm(pa, pb, 0x5410); alo[0] = __byte_perm(pa, pb, 0x7632);
            ahi[1] = __byte_perm(pc, pd, 0x5410); alo[1] = __byte_perm(pc, pd, 0x7632);
            ahi[2] = __byte_perm(pe, pf, 0x5410); alo[2] = __byte_perm(pe, pf, 0x7632);
            ahi[3] = __byte_perm(pg, ph, 0x5410); alo[3] = __byte_perm(pg, ph, 0x7632);
#pragma unroll
            for (int nt = 0; nt < 5; nt++) {
                uint2 wv = ws2[(kc * 4 + tig) * 42 + nt * 8 + gid];
                mma16816(acc[nt], ahi, wv.x, wv.y);  // hi * B
                mma16816(acc[nt], alo, wv.x, wv.y);  // lo * B
            }
        }
#pragma unroll
        for (int nt = 0; nt < 5; nt++) {
            int cb = nt * 8 + 2 * tig;
            zs[rA * 42 + cb] = acc[nt][0];  zs[rA * 42 + cb + 1] = acc[nt][1];
            zs[rB * 42 + cb] = acc[nt][2];  zs[rB * 42 + cb + 1] = acc[nt][3];
        }
        __syncthreads();
        for (int i = tid; i < 720; i += 512) {
            int oc = i / 144, r2 = i - oc * 144, od = r2 / 12, ot = r2 - od * 12;
            float s = __ldg(&b1[oc]);
#pragma unroll
            for (int kt = 0; kt < 7; kt++)
                s += zs[(od * 20 + ot + kt) * 42 + oc * 8 + kt];
            s = fmaxf(s, 0.f);
            g_h1p[((((size_t)b * 5 + oc) * 12 + oh) * 12 + ow0 + owl) * 144 + od * 12 + ot] = psh(s);
        }
        __syncthreads();
    }
}

// ---------------------------------------------------------------------------
// conv2: CTA=(b, oh, ow). 320 thr (10 warps). GEMM M80(72) x N80 x K1728.
// B staged in 4-kc chunks (27), double-buffered cp.async. 2-term fp16.
// SMEM: xs 35280 | zero 96 | bq 2*16*82 uint2 = 5248 u32 | zs 6560 = 188736 B
// ---------------------------------------------------------------------------
__global__ __launch_bounds__(320, 1)
void conv2_mma(const float* __restrict__ b2)
{
    extern __shared__ u32 sm2[];
    u32*   xs = sm2;                             // 35280 (+96 zero pad)
    uint2* bq = (uint2*)(sm2 + 35376);           // 2 * 16 * 82 uint2
    float* zs = (float*)(sm2 + 35376 + 5248);    // 80*82 f32

    const int bid = blockIdx.x;
    const int b = bid / 36, r0 = bid % 36, oh = r0 / 6, ow = r0 % 6;
    const int tid = threadIdx.x;
    const u32 bq_s = (u32)__cvta_generic_to_shared(bq);

    // prologue: chunk 0 -> buf 0 (16 rows x 80 uint2 = 640 cp16)
#pragma unroll
    for (int s = 0; s < 2; s++) {
        int j = tid + s * 320;           // 0..639
        int r = j / 40, cp = j % 40;     // col pair
        cp16(bq_s + (u32)(r * 82 + 2 * cp) * 8, &g_w2p[r * 80 + 2 * cp]);
    }
    cp_commit();

    if (tid < 96) xs[35280 + tid] = 0u;
    for (int j = tid; j < 8820; j += 320) {
        int seg = j / 36, off = j % 36;
        int ic = seg / 49, r3 = seg - ic * 49, kh = r3 / 7, kw = r3 - kh * 7;
        *(uint4*)&xs[seg * 144 + off * 4] =
            *(const uint4*)(g_h1p + ((((size_t)b * 5 + ic) * 12 + oh + kh) * 12 + ow + kw) * 144 + off * 4);
    }

    const int lane = tid & 31, wid = tid >> 5, gid = lane >> 2, tig = lane & 3;
    const int mg = wid % 5, ng = wid / 5;
    const int rA = mg * 16 + gid, rB = rA + 8;

    float acc[5][4];
#pragma unroll
    for (int nt = 0; nt < 5; nt++)
#pragma unroll
        for (int q = 0; q < 4; q++) acc[nt][q] = 0.f;

    for (int ch = 0; ch < 27; ch++) {
        const int buf = ch & 1;
        if (ch < 26) {
            const int base = (ch + 1) * 16;
#pragma unroll
            for (int s = 0; s < 2; s++) {
                int j = tid + s * 320;
                int r = j / 40, cp = j % 40;
                cp16(bq_s + (u32)(((buf ^ 1) * 16 + r) * 82 + 2 * cp) * 8,
                     &g_w2p[(base + r) * 80 + 2 * cp]);
            }
            cp_commit();
            cp_wait1();
        } else {
            cp_wait0();
        }
        __syncthreads();

#pragma unroll 1
        for (int kk = 0; kk < 4; kk++) {
            const int kc = ch * 4 + kk;
            int xo[4];
#pragma unroll
            for (int q = 0; q < 4; q++) {
                int k = kc * 16 + 2 * tig + (q & 1) + (q >> 1) * 8;
                int seg = k / 7, kd = k - seg * 7;
                xo[q] = (k >= 1715) ? 35280 : seg * 144 + kd * 12;
            }
            u32 pa = xs[xo[0] + rA], pb = xs[xo[1] + rA];
            u32 pc = xs[xo[0] + rB], pd = xs[xo[1] + rB];
            u32 pe = xs[xo[2] + rA], pf = xs[xo[3] + rA];
            u32 pg = xs[xo[2] + rB], ph = xs[xo[3] + rB];
            u32 ahi[4], alo[4];
            ahi[0] = __byte_perm(pa, pb, 0x5410); alo[0] = __byte_perm(pa, pb, 0x7632);
            ahi[1] = __byte_perm(pc, pd, 0x5410); alo[1] = __byte_perm(pc, pd, 0x7632);
            ahi[2] = __byte_perm(pe, pf, 0x5410); alo[2] = __byte_perm(pe, pf, 0x7632);
            ahi[3] = __byte_perm(pg, ph, 0x5410); alo[3] = __byte_perm(pg, ph, 0x7632);
#pragma unroll
            for (int nt = 0; nt < 5; nt++) {
                uint2 wv = bq[(buf * 16 + kk * 4 + tig) * 82 + ng * 40 + nt * 8 + gid];
                mma16816(acc[nt], ahi, wv.x, wv.y);
                mma16816(acc[nt], alo, wv.x, wv.y);
            }
        }
        __syncthreads();
    }

#pragma unroll
    for (int nt = 0; nt < 5; nt++) {
        int cb = ng * 40 + nt * 8 + 2 * tig;
        zs[rA * 82 + cb] = acc[nt][0];  zs[rA * 82 + cb + 1] = acc[nt][1];
        zs[rB * 82 + cb] = acc[nt][2];  zs[rB * 82 + cb + 1] = acc[nt][3];
    }
    __syncthreads();
    for (int i = tid; i < 360; i += 320) {
        int oc = i / 36, r2 = i - oc * 36, od = r2 / 6, ot = r2 - od * 6;
        float s = __ldg(&b2[oc]);
#pragma unroll
        for (int kt = 0; kt < 7; kt++)
            s += zs[(od * 12 + ot + kt) * 82 + oc * 8 + kt];
        s = fmaxf(s, 0.f);
        g_h2[(size_t)b * 12960 + oc * 1296 + oh * 216 + ow * 36 + od * 6 + ot] = s;
    }
}

// ---------------------------------------------------------------------------
__global__ __launch_bounds__(256)
void linear_kernel(const float* __restrict__ wl, const float* __restrict__ bl,
                   float* __restrict__ out)
{
    const int b = blockIdx.x;
    const float* h = g_h2 + (size_t)b * 12960;
    float s = 0.f;
    for (int i = threadIdx.x; i < 12960; i += 256) s = fmaf(h[i], wl[i], s);
    __shared__ float red[8];
#pragma unroll
    for (int o = 16; o; o >>= 1) s += __shfl_xor_sync(0xFFFFFFFFu, s, o);
    if ((threadIdx.x & 31) == 0) red[threadIdx.x >> 5] = s;
    __syncthreads();
    if (threadIdx.x < 32) {
        s = (threadIdx.x < 8) ? red[threadIdx.x] : 0.f;
#pragma unroll
        for (int o = 4; o; o >>= 1) s += __shfl_xor_sync(0xFFFFFFFFu, s, o);
        if (threadIdx.x == 0) out[b] = 1.f / (1.f + expf(-(s + bl[0])));
    }
}

// ---------------------------------------------------------------------------
extern "C" void kernel_launch(void* const* d_in, const int* in_sizes, int n_in,
                              void* d_out, int out_size)
{
    const float* x    = (const float*)d_in[0];
    const float* w1   = (const float*)d_in[1];
    const float* b1   = (const float*)d_in[2];
    const float* w2   = (const float*)d_in[3];
    const float* b2   = (const float*)d_in[4];
    const float* wlin = (const float*)d_in[5];
    const float* blin = (const float*)d_in[6];
    float* out = (float*)d_out;

    const size_t smem1 = (30560 + 7392 + 10752) * 4;     // 194816 B
    const size_t smem2 = (35376 + 5248 + 6560) * 4;      // 188736 B
    cudaFuncSetAttribute(conv1_mma, cudaFuncAttributeMaxDynamicSharedMemorySize, (int)smem1);
    cudaFuncSetAttribute(conv2_mma, cudaFuncAttributeMaxDynamicSharedMemorySize, (int)smem2);

    pack_x<<<(NB * 324 * 360 + 255) / 256, 256>>>(x);
    pack_w1<<<14, 256>>>(w1);
    pack_w2<<<135, 256>>>(w2);
    conv1_mma<<<NB * 24, 512, smem1>>>(b1);
    conv2_mma<<<NB * 36, 320, smem2>>>(b2);
    linear_kernel<<<NB, 256>>>(wlin, blin, out);
}

// round 8
// speedup vs baseline: 1.6425x; 1.3350x over previous
#include <cuda_runtime.h>
#include <cuda_fp16.h>
typedef unsigned int u32;
#define NB 128

// ---------------------------------------------------------------------------
// Globals (no cudaMalloc allowed)
// ---------------------------------------------------------------------------
__device__ __align__(16) u32   g_xp[NB * 18 * 18 * 360];          // x split-packed fp16, d-stride 20
__device__ __align__(16) u32   g_h1p[NB * 5 * 12 * 12 * 144];     // conv1 out split-packed fp16
__device__ float               g_h2[NB * 10 * 1296];
__device__ __align__(16) uint2 g_w1p[22 * 4 * 40];                // B1 fp16 fragments
__device__ __align__(16) uint2 g_w2p[108 * 4 * 80];               // B2 fp16 fragments

// ---------------------------------------------------------------------------
__device__ __forceinline__ u32 psh(float v) {   // split-pack: fp16 hi | fp16 lo<<16
    __half h = __float2half_rn(v);
    __half l = __float2half_rn(v - __half2float(h));
    return (u32)__half_as_ushort(h) | ((u32)__half_as_ushort(l) << 16);
}
__device__ __forceinline__ u32 ph2(float v0, float v1) {
    return (u32)__half_as_ushort(__float2half_rn(v0))
         | ((u32)__half_as_ushort(__float2half_rn(v1)) << 16);
}
__device__ __forceinline__ void mma16816(float* c, const u32* a, u32 b0, u32 b1) {
    asm volatile("mma.sync.aligned.m16n8k16.row.col.f32.f16.f16.f32 "
        "{%0,%1,%2,%3},{%4,%5,%6,%7},{%8,%9},{%0,%1,%2,%3};"
        : "+f"(c[0]), "+f"(c[1]), "+f"(c[2]), "+f"(c[3])
        : "r"(a[0]), "r"(a[1]), "r"(a[2]), "r"(a[3]), "r"(b0), "r"(b1));
}
__device__ __forceinline__ void cp16(u32 dst, const void* src) {
    asm volatile("cp.async.cg.shared.global [%0], [%1], 16;" :: "r"(dst), "l"(src));
}
__device__ __forceinline__ void cp_commit() { asm volatile("cp.async.commit_group;"); }
__device__ __forceinline__ void cp_wait0()  { asm volatile("cp.async.wait_group 0;"); }
__device__ __forceinline__ void cp_wait1()  { asm volatile("cp.async.wait_group 1;"); }

// ---------------------------------------------------------------------------
// pack kernels
// ---------------------------------------------------------------------------
__global__ void pack_x(const float* __restrict__ x) {
    int i = blockIdx.x * 256 + threadIdx.x;
    if (i >= NB * 324 * 360) return;
    int seg = i / 360, r = i % 360, d = r / 20, t = r % 20;
    g_xp[i] = (t < 18) ? psh(x[(size_t)seg * 324 + d * 18 + t]) : 0u;
}
__global__ void pack_w1(const float* __restrict__ w1) {
    int i = blockIdx.x * 256 + threadIdx.x;
    if (i >= 3520) return;
    int kcti = i / 40, n = i % 40, oc = n >> 3, kt = n & 7;
    int k0 = (kcti >> 2) * 16 + 2 * (kcti & 3);
    float v[4];
#pragma unroll
    for (int j = 0; j < 4; j++) {
        int k = k0 + (j & 1) + (j >> 1) * 8;
        v[j] = (k < 343 && kt < 7) ? w1[oc * 2401 + k * 7 + kt] : 0.f;
    }
    uint2 o; o.x = ph2(v[0], v[1]); o.y = ph2(v[2], v[3]);
    g_w1p[i] = o;
}
__global__ void pack_w2(const float* __restrict__ w2) {
    int i = blockIdx.x * 256 + threadIdx.x;
    if (i >= 34560) return;
    int kcti = i / 80, n = i % 80, oc = n >> 3, kt = n & 7;
    int k0 = (kcti >> 2) * 16 + 2 * (kcti & 3);
    float v[4];
#pragma unroll
    for (int j = 0; j < 4; j++) {
        int k = k0 + (j & 1) + (j >> 1) * 8;
        v[j] = 0.f;
        if (k < 1715 && kt < 7) {
            int ic = k / 343, t3 = k - ic * 343;
            v[j] = w2[(size_t)oc * 12005 + ic * 2401 + t3 * 7 + kt];
        }
    }
    uint2 o; o.x = ph2(v[0], v[1]); o.y = ph2(v[2], v[3]);
    g_w2p[i] = o;
}

// ---------------------------------------------------------------------------
// conv1: CTA=(b, oh, ow-half). 512 thr (16 warps). 3 passes x 2 owl.
// Full-unrolled kc loop, offsets from SMEM table, B fragments reused x2 owl.
// SMEM layout (u32): xs[0,32320) (zero pad at 30240+) | tbl[32320,32672)
//                    ws2 @32672 (7392) | zs @40064 (10752 f32)  => 203264 B
// ---------------------------------------------------------------------------
__global__ __launch_bounds__(512, 1)
void conv1_mma(const float* __restrict__ b1)
{
    extern __shared__ u32 sm[];
    u32*   xs   = sm;
    u32*   tbl  = sm + 32320;
    uint4* tb4  = (uint4*)tbl;
    uint2* ws2  = (uint2*)(sm + 32672);
    float* zs   = (float*)(sm + 40064);

    const int bid = blockIdx.x;
    const int b = bid / 24, r0 = bid % 24, oh = r0 >> 1, ow0 = (r0 & 1) * 6;
    const int tid = threadIdx.x;

    // offset table: tbl[kc*16 + tig*4 + q]
    if (tid < 352) {
        int kc = tid >> 4, tg = (tid >> 2) & 3, q = tid & 3;
        int k = kc * 16 + 2 * tg + (q & 1) + (q >> 1) * 8;
        u32 off = 30240u;
        if (k < 343) {
            int kh = k / 49, rm = k - kh * 49, kw = rm / 7, kd = rm - kw * 7;
            off = (u32)((kh * 12 + kw) * 360 + kd * 20);
        }
        tbl[tid] = off;
    }
    for (int i = tid; i < 3520; i += 512) ws2[(i / 40) * 42 + i % 40] = g_w1p[i];
    for (int i = tid; i < 2080; i += 512) xs[30240 + i] = 0u;
    const u32* xb = g_xp + (((size_t)b * 18 + oh) * 18 + ow0) * 360;
    for (int j = tid; j < 7560; j += 512) {
        int seg = j / 90, off = j % 90;
        *(uint4*)&xs[seg * 360 + off * 4] =
            *(const uint4*)(xb + ((size_t)(seg / 12) * 18 + seg % 12) * 360 + off * 4);
    }
    __syncthreads();

    const int lane = tid & 31, wid = tid >> 5, gid = lane >> 2, tig = lane & 3;
    const int rA = wid * 16 + gid;

    for (int p = 0; p < 3; p++) {
        const int bA = p * 720 + rA;             // owl0 = 2p
        float acc0[5][4], acc1[5][4];
#pragma unroll
        for (int nt = 0; nt < 5; nt++)
#pragma unroll
            for (int q = 0; q < 4; q++) { acc0[nt][q] = 0.f; acc1[nt][q] = 0.f; }

#pragma unroll
        for (int kc = 0; kc < 22; kc++) {
            const uint4 off = tb4[kc * 4 + tig];
            const u32 a0 = off.x + bA, a1 = off.y + bA, a2 = off.z + bA, a3 = off.w + bA;
            // owl0
            u32 pa = xs[a0],      pb = xs[a1];
            u32 pc = xs[a0 + 8],  pd = xs[a1 + 8];
            u32 pe = xs[a2],      pf = xs[a3];
            u32 pg = xs[a2 + 8],  ph = xs[a3 + 8];
            u32 h0[4], l0[4];
            h0[0] = __byte_perm(pa, pb, 0x5410); l0[0] = __byte_perm(pa, pb, 0x7632);
            h0[1] = __byte_perm(pc, pd, 0x5410); l0[1] = __byte_perm(pc, pd, 0x7632);
            h0[2] = __byte_perm(pe, pf, 0x5410); l0[2] = __byte_perm(pe, pf, 0x7632);
            h0[3] = __byte_perm(pg, ph, 0x5410); l0[3] = __byte_perm(pg, ph, 0x7632);
            // owl1 = owl0+1 -> +360
            u32 qa = xs[a0 + 360], qb = xs[a1 + 360];
            u32 qc = xs[a0 + 368], qd = xs[a1 + 368];
            u32 qe = xs[a2 + 360], qf = xs[a3 + 360];
            u32 qg = xs[a2 + 368], qh = xs[a3 + 368];
            u32 h1[4], l1[4];
            h1[0] = __byte_perm(qa, qb, 0x5410); l1[0] = __byte_perm(qa, qb, 0x7632);
            h1[1] = __byte_perm(qc, qd, 0x5410); l1[1] = __byte_perm(qc, qd, 0x7632);
            h1[2] = __byte_perm(qe, qf, 0x5410); l1[2] = __byte_perm(qe, qf, 0x7632);
            h1[3] = __byte_perm(qg, qh, 0x5410); l1[3] = __byte_perm(qg, qh, 0x7632);
#pragma unroll
            for (int nt = 0; nt < 5; nt++) {
                uint2 wv = ws2[(kc * 4 + tig) * 42 + nt * 8 + gid];
                mma16816(acc0[nt], h0, wv.x, wv.y);
                mma16816(acc0[nt], l0, wv.x, wv.y);
                mma16816(acc1[nt], h1, wv.x, wv.y);
                mma16816(acc1[nt], l1, wv.x, wv.y);
            }
        }

        // two epilogues (zs single-buffered)
#pragma unroll
        for (int e = 0; e < 2; e++) {
            float (*ac)[4] = e ? acc1 : acc0;
            const int owl = 2 * p + e;
#pragma unroll
            for (int nt = 0; nt < 5; nt++) {
                int cb = nt * 8 + 2 * tig;
                zs[rA * 42 + cb]       = ac[nt][0];  zs[rA * 42 + cb + 1]       = ac[nt][1];
                zs[(rA + 8) * 42 + cb] = ac[nt][2];  zs[(rA + 8) * 42 + cb + 1] = ac[nt][3];
            }
            __syncthreads();
            for (int i = tid; i < 720; i += 512) {
                int oc = i / 144, r2 = i - oc * 144, od = r2 / 12, ot = r2 - od * 12;
                float s = __ldg(&b1[oc]);
#pragma unroll
                for (int kt = 0; kt < 7; kt++)
                    s += zs[(od * 20 + ot + kt) * 42 + oc * 8 + kt];
                s = fmaxf(s, 0.f);
                g_h1p[((((size_t)b * 5 + oc) * 12 + oh) * 12 + ow0 + owl) * 144 + od * 12 + ot] = psh(s);
            }
            __syncthreads();
        }
    }
}

// ---------------------------------------------------------------------------
// conv2: CTA=(b, oh, ow). 320 thr (10 warps). GEMM M80(72) x N80 x K1728.
// Offset table + unrolled kk; B in 4-kc chunks, double-buffered cp.async.
// SMEM (u32): xs[0,35376) | tbl2 @35376 (1728) | bq @37104 (5248) | zs @42352 (6560)
//   => 195648 B
// ---------------------------------------------------------------------------
__global__ __launch_bounds__(320, 1)
void conv2_mma(const float* __restrict__ b2)
{
    extern __shared__ u32 sm2[];
    u32*   xs   = sm2;
    u32*   tbl  = sm2 + 35376;
    uint4* tb4  = (uint4*)tbl;
    uint2* bq   = (uint2*)(sm2 + 37104);
    float* zs   = (float*)(sm2 + 42352);

    const int bid = blockIdx.x;
    const int b = bid / 36, r0 = bid % 36, oh = r0 / 6, ow = r0 % 6;
    const int tid = threadIdx.x;
    const u32 bq_s = (u32)__cvta_generic_to_shared(bq);

    // prologue: chunk 0 -> buf 0
#pragma unroll
    for (int s = 0; s < 2; s++) {
        int j = tid + s * 320;
        int r = j / 40, cp = j % 40;
        cp16(bq_s + (u32)(r * 82 + 2 * cp) * 8, &g_w2p[r * 80 + 2 * cp]);
    }
    cp_commit();

    // offset table: tbl[kc*16 + tig*4 + q]
    for (int i = tid; i < 1728; i += 320) {
        int kc = i >> 4, tg = (i >> 2) & 3, q = i & 3;
        int k = kc * 16 + 2 * tg + (q & 1) + (q >> 1) * 8;
        u32 off = 35280u;
        if (k < 1715) { int seg = k / 7, kd = k - seg * 7; off = (u32)(seg * 144 + kd * 12); }
        tbl[i] = off;
    }
    if (tid < 96) xs[35280 + tid] = 0u;
    for (int j = tid; j < 8820; j += 320) {
        int seg = j / 36, off = j % 36;
        int ic = seg / 49, r3 = seg - ic * 49, kh = r3 / 7, kw = r3 - kh * 7;
        *(uint4*)&xs[seg * 144 + off * 4] =
            *(const uint4*)(g_h1p + ((((size_t)b * 5 + ic) * 12 + oh + kh) * 12 + ow + kw) * 144 + off * 4);
    }

    const int lane = tid & 31, wid = tid >> 5, gid = lane >> 2, tig = lane & 3;
    const int mg = wid % 5, ng = wid / 5;
    const int rA = mg * 16 + gid, rB = rA + 8;

    float acc[5][4];
#pragma unroll
    for (int nt = 0; nt < 5; nt++)
#pragma unroll
        for (int q = 0; q < 4; q++) acc[nt][q] = 0.f;

    for (int ch = 0; ch < 27; ch++) {
        const int buf = ch & 1;
        if (ch < 26) {
            const int base = (ch + 1) * 16;
#pragma unroll
            for (int s = 0; s < 2; s++) {
                int j = tid + s * 320;
                int r = j / 40, cp = j % 40;
                cp16(bq_s + (u32)(((buf ^ 1) * 16 + r) * 82 + 2 * cp) * 8,
                     &g_w2p[(base + r) * 80 + 2 * cp]);
            }
            cp_commit();
            cp_wait1();
        } else {
            cp_wait0();
        }
        __syncthreads();

#pragma unroll
        for (int kk = 0; kk < 4; kk++) {
            const uint4 off = tb4[(ch * 4 + kk) * 4 + tig];
            u32 pa = xs[off.x + rA], pb = xs[off.y + rA];
            u32 pc = xs[off.x + rB], pd = xs[off.y + rB];
            u32 pe = xs[off.z + rA], pf = xs[off.w + rA];
            u32 pg = xs[off.z + rB], ph = xs[off.w + rB];
            u32 ahi[4], alo[4];
            ahi[0] = __byte_perm(pa, pb, 0x5410); alo[0] = __byte_perm(pa, pb, 0x7632);
            ahi[1] = __byte_perm(pc, pd, 0x5410); alo[1] = __byte_perm(pc, pd, 0x7632);
            ahi[2] = __byte_perm(pe, pf, 0x5410); alo[2] = __byte_perm(pe, pf, 0x7632);
            ahi[3] = __byte_perm(pg, ph, 0x5410); alo[3] = __byte_perm(pg, ph, 0x7632);
#pragma unroll
            for (int nt = 0; nt < 5; nt++) {
                uint2 wv = bq[(buf * 16 + kk * 4 + tig) * 82 + ng * 40 + nt * 8 + gid];
                mma16816(acc[nt], ahi, wv.x, wv.y);
                mma16816(acc[nt], alo, wv.x, wv.y);
            }
        }
        __syncthreads();
    }

#pragma unroll
    for (int nt = 0; nt < 5; nt++) {
        int cb = ng * 40 + nt * 8 + 2 * tig;
        zs[rA * 82 + cb] = acc[nt][0];  zs[rA * 82 + cb + 1] = acc[nt][1];
        zs[rB * 82 + cb] = acc[nt][2];  zs[rB * 82 + cb + 1] = acc[nt][3];
    }
    __syncthreads();
    for (int i = tid; i < 360; i += 320) {
        int oc = i / 36, r2 = i - oc * 36, od = r2 / 6, ot = r2 - od * 6;
        float s = __ldg(&b2[oc]);
#pragma unroll
        for (int kt = 0; kt < 7; kt++)
            s += zs[(od * 12 + ot + kt) * 82 + oc * 8 + kt];
        s = fmaxf(s, 0.f);
        g_h2[(size_t)b * 12960 + oc * 1296 + oh * 216 + ow * 36 + od * 6 + ot] = s;
    }
}

// ---------------------------------------------------------------------------
__global__ __launch_bounds__(256)
void linear_kernel(const float* __restrict__ wl, const float* __restrict__ bl,
                   float* __restrict__ out)
{
    const int b = blockIdx.x;
    const float* h = g_h2 + (size_t)b * 12960;
    float s = 0.f;
    for (int i = threadIdx.x; i < 12960; i += 256) s = fmaf(h[i], wl[i], s);
    __shared__ float red[8];
#pragma unroll
    for (int o = 16; o; o >>= 1) s += __shfl_xor_sync(0xFFFFFFFFu, s, o);
    if ((threadIdx.x & 31) == 0) red[threadIdx.x >> 5] = s;
    __syncthreads();
    if (threadIdx.x < 32) {
        s = (threadIdx.x < 8) ? red[threadIdx.x] : 0.f;
#pragma unroll
        for (int o = 4; o; o >>= 1) s += __shfl_xor_sync(0xFFFFFFFFu, s, o);
        if (threadIdx.x == 0) out[b] = 1.f / (1.f + expf(-(s + bl[0])));
    }
}

// ---------------------------------------------------------------------------
extern "C" void kernel_launch(void* const* d_in, const int* in_sizes, int n_in,
                              void* d_out, int out_size)
{
    const float* x    = (const float*)d_in[0];
    const float* w1   = (const float*)d_in[1];
    const float* b1   = (const float*)d_in[2];
    const float* w2   = (const float*)d_in[3];
    const float* b2   = (const float*)d_in[4];
    const float* wlin = (const float*)d_in[5];
    const float* blin = (const float*)d_in[6];
    float* out = (float*)d_out;

    const size_t smem1 = 50816u * 4;   // 203264 B
    const size_t smem2 = 48912u * 4;   // 195648 B
    cudaFuncSetAttribute(conv1_mma, cudaFuncAttributeMaxDynamicSharedMemorySize, (int)smem1);
    cudaFuncSetAttribute(conv2_mma, cudaFuncAttributeMaxDynamicSharedMemorySize, (int)smem2);

    pack_x<<<(NB * 324 * 360 + 255) / 256, 256>>>(x);
    pack_w1<<<14, 256>>>(w1);
    pack_w2<<<135, 256>>>(w2);
    conv1_mma<<<NB * 24, 512, smem1>>>(b1);
    conv2_mma<<<NB * 36, 320, smem2>>>(b2);
    linear_kernel<<<NB, 256>>>(wlin, blin, out);
}

// round 10
// speedup vs baseline: 1.9240x; 1.1714x over previous
#include <cuda_runtime.h>
#include <cuda_fp16.h>
typedef unsigned int u32;
#define NB 128

// ---------------------------------------------------------------------------
// Globals (no cudaMalloc allowed)
// ---------------------------------------------------------------------------
__device__ __align__(16) u32   g_xp[NB * 18 * 18 * 360];          // x split-packed fp16, d-stride 20
__device__ __align__(16) u32   g_h1p[NB * 5 * 12 * 12 * 144];     // conv1 out split-packed fp16
__device__ float               g_h2[NB * 10 * 1296];
__device__ __align__(16) uint2 g_w1p[22 * 4 * 40];                // B1 fp16 fragments
__device__ __align__(16) uint2 g_w2p[108 * 4 * 80];               // B2 fp16 fragments

// ---------------------------------------------------------------------------
__device__ __forceinline__ u32 psh(float v) {   // split-pack: fp16 hi | fp16 lo<<16
    __half h = __float2half_rn(v);
    __half l = __float2half_rn(v - __half2float(h));
    return (u32)__half_as_ushort(h) | ((u32)__half_as_ushort(l) << 16);
}
__device__ __forceinline__ u32 ph2(float v0, float v1) {
    return (u32)__half_as_ushort(__float2half_rn(v0))
         | ((u32)__half_as_ushort(__float2half_rn(v1)) << 16);
}
__device__ __forceinline__ void mma16816(float* c, const u32* a, u32 b0, u32 b1) {
    asm volatile("mma.sync.aligned.m16n8k16.row.col.f32.f16.f16.f32 "
        "{%0,%1,%2,%3},{%4,%5,%6,%7},{%8,%9},{%0,%1,%2,%3};"
        : "+f"(c[0]), "+f"(c[1]), "+f"(c[2]), "+f"(c[3])
        : "r"(a[0]), "r"(a[1]), "r"(a[2]), "r"(a[3]), "r"(b0), "r"(b1));
}
__device__ __forceinline__ void cp16(u32 dst, const void* src) {
    asm volatile("cp.async.cg.shared.global [%0], [%1], 16;" :: "r"(dst), "l"(src));
}
__device__ __forceinline__ void cp_commit() { asm volatile("cp.async.commit_group;"); }
__device__ __forceinline__ void cp_wait0()  { asm volatile("cp.async.wait_group 0;"); }
__device__ __forceinline__ void cp_wait1()  { asm volatile("cp.async.wait_group 1;"); }

// ---------------------------------------------------------------------------
// pack kernels
// ---------------------------------------------------------------------------
__global__ void pack_x(const float* __restrict__ x) {
    int i = blockIdx.x * 256 + threadIdx.x;
    if (i >= NB * 324 * 360) return;
    int seg = i / 360, r = i % 360, d = r / 20, t = r % 20;
    g_xp[i] = (t < 18) ? psh(x[(size_t)seg * 324 + d * 18 + t]) : 0u;
}
__global__ void pack_w1(const float* __restrict__ w1) {
    int i = blockIdx.x * 256 + threadIdx.x;
    if (i >= 3520) return;
    int kcti = i / 40, n = i % 40, oc = n >> 3, kt = n & 7;
    int k0 = (kcti >> 2) * 16 + 2 * (kcti & 3);
    float v[4];
#pragma unroll
    for (int j = 0; j < 4; j++) {
        int k = k0 + (j & 1) + (j >> 1) * 8;
        v[j] = (k < 343 && kt < 7) ? w1[oc * 2401 + k * 7 + kt] : 0.f;
    }
    uint2 o; o.x = ph2(v[0], v[1]); o.y = ph2(v[2], v[3]);
    g_w1p[i] = o;
}
__global__ void pack_w2(const float* __restrict__ w2) {
    int i = blockIdx.x * 256 + threadIdx.x;
    if (i >= 34560) return;
    int kcti = i / 80, n = i % 80, oc = n >> 3, kt = n & 7;
    int k0 = (kcti >> 2) * 16 + 2 * (kcti & 3);
    float v[4];
#pragma unroll
    for (int j = 0; j < 4; j++) {
        int k = k0 + (j & 1) + (j >> 1) * 8;
        v[j] = 0.f;
        if (k < 1715 && kt < 7) {
            int ic = k / 343, t3 = k - ic * 343;
            v[j] = w2[(size_t)oc * 12005 + ic * 2401 + t3 * 7 + kt];
        }
    }
    uint2 o; o.x = ph2(v[0], v[1]); o.y = ph2(v[2], v[3]);
    g_w2p[i] = o;
}

// ---------------------------------------------------------------------------
// conv1: CTA=(b, oh, ow-half). 512 thr (16 warps). 3 passes x 2 owl.
// (unchanged from R8 winner)
// ---------------------------------------------------------------------------
__global__ __launch_bounds__(512, 1)
void conv1_mma(const float* __restrict__ b1)
{
    extern __shared__ u32 sm[];
    u32*   xs   = sm;
    u32*   tbl  = sm + 32320;
    uint4* tb4  = (uint4*)tbl;
    uint2* ws2  = (uint2*)(sm + 32672);
    float* zs   = (float*)(sm + 40064);

    const int bid = blockIdx.x;
    const int b = bid / 24, r0 = bid % 24, oh = r0 >> 1, ow0 = (r0 & 1) * 6;
    const int tid = threadIdx.x;

    if (tid < 352) {
        int kc = tid >> 4, tg = (tid >> 2) & 3, q = tid & 3;
        int k = kc * 16 + 2 * tg + (q & 1) + (q >> 1) * 8;
        u32 off = 30240u;
        if (k < 343) {
            int kh = k / 49, rm = k - kh * 49, kw = rm / 7, kd = rm - kw * 7;
            off = (u32)((kh * 12 + kw) * 360 + kd * 20);
        }
        tbl[tid] = off;
    }
    for (int i = tid; i < 3520; i += 512) ws2[(i / 40) * 42 + i % 40] = g_w1p[i];
    for (int i = tid; i < 2080; i += 512) xs[30240 + i] = 0u;
    const u32* xb = g_xp + (((size_t)b * 18 + oh) * 18 + ow0) * 360;
    for (int j = tid; j < 7560; j += 512) {
        int seg = j / 90, off = j % 90;
        *(uint4*)&xs[seg * 360 + off * 4] =
            *(const uint4*)(xb + ((size_t)(seg / 12) * 18 + seg % 12) * 360 + off * 4);
    }
    __syncthreads();

    const int lane = tid & 31, wid = tid >> 5, gid = lane >> 2, tig = lane & 3;
    const int rA = wid * 16 + gid;

    for (int p = 0; p < 3; p++) {
        const int bA = p * 720 + rA;
        float acc0[5][4], acc1[5][4];
#pragma unroll
        for (int nt = 0; nt < 5; nt++)
#pragma unroll
            for (int q = 0; q < 4; q++) { acc0[nt][q] = 0.f; acc1[nt][q] = 0.f; }

#pragma unroll
        for (int kc = 0; kc < 22; kc++) {
            const uint4 off = tb4[kc * 4 + tig];
            const u32 a0 = off.x + bA, a1 = off.y + bA, a2 = off.z + bA, a3 = off.w + bA;
            u32 pa = xs[a0],      pb = xs[a1];
            u32 pc = xs[a0 + 8],  pd = xs[a1 + 8];
            u32 pe = xs[a2],      pf = xs[a3];
            u32 pg = xs[a2 + 8],  ph = xs[a3 + 8];
            u32 h0[4], l0[4];
            h0[0] = __byte_perm(pa, pb, 0x5410); l0[0] = __byte_perm(pa, pb, 0x7632);
            h0[1] = __byte_perm(pc, pd, 0x5410); l0[1] = __byte_perm(pc, pd, 0x7632);
            h0[2] = __byte_perm(pe, pf, 0x5410); l0[2] = __byte_perm(pe, pf, 0x7632);
            h0[3] = __byte_perm(pg, ph, 0x5410); l0[3] = __byte_perm(pg, ph, 0x7632);
            u32 qa = xs[a0 + 360], qb = xs[a1 + 360];
            u32 qc = xs[a0 + 368], qd = xs[a1 + 368];
            u32 qe = xs[a2 + 360], qf = xs[a3 + 360];
            u32 qg = xs[a2 + 368], qh = xs[a3 + 368];
            u32 h1[4], l1[4];
            h1[0] = __byte_perm(qa, qb, 0x5410); l1[0] = __byte_perm(qa, qb, 0x7632);
            h1[1] = __byte_perm(qc, qd, 0x5410); l1[1] = __byte_perm(qc, qd, 0x7632);
            h1[2] = __byte_perm(qe, qf, 0x5410); l1[2] = __byte_perm(qe, qf, 0x7632);
            h1[3] = __byte_perm(qg, qh, 0x5410); l1[3] = __byte_perm(qg, qh, 0x7632);
#pragma unroll
            for (int nt = 0; nt < 5; nt++) {
                uint2 wv = ws2[(kc * 4 + tig) * 42 + nt * 8 + gid];
                mma16816(acc0[nt], h0, wv.x, wv.y);
                mma16816(acc0[nt], l0, wv.x, wv.y);
                mma16816(acc1[nt], h1, wv.x, wv.y);
                mma16816(acc1[nt], l1, wv.x, wv.y);
            }
        }

#pragma unroll
        for (int e = 0; e < 2; e++) {
            float (*ac)[4] = e ? acc1 : acc0;
            const int owl = 2 * p + e;
#pragma unroll
            for (int nt = 0; nt < 5; nt++) {
                int cb = nt * 8 + 2 * tig;
                zs[rA * 42 + cb]       = ac[nt][0];  zs[rA * 42 + cb + 1]       = ac[nt][1];
                zs[(rA + 8) * 42 + cb] = ac[nt][2];  zs[(rA + 8) * 42 + cb + 1] = ac[nt][3];
            }
            __syncthreads();
            for (int i = tid; i < 720; i += 512) {
                int oc = i / 144, r2 = i - oc * 144, od = r2 / 12, ot = r2 - od * 12;
                float s = __ldg(&b1[oc]);
#pragma unroll
                for (int kt = 0; kt < 7; kt++)
                    s += zs[(od * 20 + ot + kt) * 42 + oc * 8 + kt];
                s = fmaxf(s, 0.f);
                g_h1p[((((size_t)b * 5 + oc) * 12 + oh) * 12 + ow0 + owl) * 144 + od * 12 + ot] = psh(s);
            }
            __syncthreads();
        }
    }
}

// ---------------------------------------------------------------------------
// conv2: CTA=(b, oh, ow-pair). 320 thr (10 warps). 2 ow per CTA -> B amortized.
// xs: [5 ic][7 kh][8 w] x 144 = 40320 u32 (+240 zero pad).
// SMEM (u32): xs[0,40560) | tbl @40560 (1728) | bq @42288 (5248) | zs @47536 (6560)
//   => 54096 u32 = 216384 B
// ---------------------------------------------------------------------------
__global__ __launch_bounds__(320, 1)
void conv2_mma(const float* __restrict__ b2)
{
    extern __shared__ u32 sm2[];
    u32*   xs   = sm2;
    u32*   tbl  = sm2 + 40560;
    uint4* tb4  = (uint4*)tbl;
    uint2* bq   = (uint2*)(sm2 + 42288);
    float* zs   = (float*)(sm2 + 47536);

    const int bid = blockIdx.x;
    const int b = bid / 18, r0 = bid % 18;
    const int oh = r0 / 3, ow0 = (r0 % 3) * 2;
    const int tid = threadIdx.x;
    const u32 bq_s = (u32)__cvta_generic_to_shared(bq);

    // prologue: B chunk 0 -> buf 0
#pragma unroll
    for (int s = 0; s < 2; s++) {
        int j = tid + s * 320;
        int r = j / 40, cp = j % 40;
        cp16(bq_s + (u32)(r * 82 + 2 * cp) * 8, &g_w2p[r * 80 + 2 * cp]);
    }
    cp_commit();

    // offset table: layout seg' = (ic*7+kh)*8 + kw, off = seg'*144 + kd*12
    for (int i = tid; i < 1728; i += 320) {
        int kc = i >> 4, tg = (i >> 2) & 3, q = i & 3;
        int k = kc * 16 + 2 * tg + (q & 1) + (q >> 1) * 8;
        u32 off = 40320u;
        if (k < 1715) {
            int ic = k / 343, rm = k - ic * 343;
            int kh = rm / 49, rm2 = rm - kh * 49;
            int kw = rm2 / 7, kd = rm2 - kw * 7;
            off = (u32)(((ic * 7 + kh) * 8 + kw) * 144 + kd * 12);
        }
        tbl[i] = off;
    }
    for (int i = tid; i < 240; i += 320) xs[40320 + i] = 0u;
    // stage xs: 280 segs x 36 uint4
    for (int j = tid; j < 10080; j += 320) {
        int seg = j / 36, off = j % 36;
        int ic = seg / 56, r3 = seg - ic * 56;
        int kh = r3 / 8, w = r3 - kh * 8;
        *(uint4*)&xs[seg * 144 + off * 4] =
            *(const uint4*)(g_h1p + ((((size_t)b * 5 + ic) * 12 + oh + kh) * 12 + ow0 + w) * 144 + off * 4);
    }

    const int lane = tid & 31, wid = tid >> 5, gid = lane >> 2, tig = lane & 3;
    const int mg = wid % 5, ng = wid / 5;
    const int rA = mg * 16 + gid, rB = rA + 8;

    float acc0[5][4], acc1[5][4];
#pragma unroll
    for (int nt = 0; nt < 5; nt++)
#pragma unroll
        for (int q = 0; q < 4; q++) { acc0[nt][q] = 0.f; acc1[nt][q] = 0.f; }

    for (int ch = 0; ch < 27; ch++) {
        const int buf = ch & 1;
        if (ch < 26) {
            const int base = (ch + 1) * 16;
#pragma unroll
            for (int s = 0; s < 2; s++) {
                int j = tid + s * 320;
                int r = j / 40, cp = j % 40;
                cp16(bq_s + (u32)(((buf ^ 1) * 16 + r) * 82 + 2 * cp) * 8,
                     &g_w2p[(base + r) * 80 + 2 * cp]);
            }
            cp_commit();
            cp_wait1();
        } else {
            cp_wait0();
        }
        __syncthreads();

#pragma unroll
        for (int kk = 0; kk < 4; kk++) {
            const uint4 off = tb4[(ch * 4 + kk) * 4 + tig];
            // ow0
            u32 pa = xs[off.x + rA], pb = xs[off.y + rA];
            u32 pc = xs[off.x + rB], pd = xs[off.y + rB];
            u32 pe = xs[off.z + rA], pf = xs[off.w + rA];
            u32 pg = xs[off.z + rB], ph = xs[off.w + rB];
            u32 h0[4], l0[4];
            h0[0] = __byte_perm(pa, pb, 0x5410); l0[0] = __byte_perm(pa, pb, 0x7632);
            h0[1] = __byte_perm(pc, pd, 0x5410); l0[1] = __byte_perm(pc, pd, 0x7632);
            h0[2] = __byte_perm(pe, pf, 0x5410); l0[2] = __byte_perm(pe, pf, 0x7632);
            h0[3] = __byte_perm(pg, ph, 0x5410); l0[3] = __byte_perm(pg, ph, 0x7632);
            // ow1 = ow0+1 -> +144
            u32 qa = xs[off.x + 144 + rA], qb = xs[off.y + 144 + rA];
            u32 qc = xs[off.x + 144 + rB], qd = xs[off.y + 144 + rB];
            u32 qe = xs[off.z + 144 + rA], qf = xs[off.w + 144 + rA];
            u32 qg = xs[off.z + 144 + rB], qh = xs[off.w + 144 + rB];
            u32 h1[4], l1[4];
            h1[0] = __byte_perm(qa, qb, 0x5410); l1[0] = __byte_perm(qa, qb, 0x7632);
            h1[1] = __byte_perm(qc, qd, 0x5410); l1[1] = __byte_perm(qc, qd, 0x7632);
            h1[2] = __byte_perm(qe, qf, 0x5410); l1[2] = __byte_perm(qe, qf, 0x7632);
            h1[3] = __byte_perm(qg, qh, 0x5410); l1[3] = __byte_perm(qg, qh, 0x7632);
#pragma unroll
            for (int nt = 0; nt < 5; nt++) {
                uint2 wv = bq[(buf * 16 + kk * 4 + tig) * 82 + ng * 40 + nt * 8 + gid];
                mma16816(acc0[nt], h0, wv.x, wv.y);
                mma16816(acc0[nt], l0, wv.x, wv.y);
                mma16816(acc1[nt], h1, wv.x, wv.y);
                mma16816(acc1[nt], l1, wv.x, wv.y);
            }
        }
        __syncthreads();
    }

#pragma unroll
    for (int e = 0; e < 2; e++) {
        float (*ac)[4] = e ? acc1 : acc0;
#pragma unroll
        for (int nt = 0; nt < 5; nt++) {
            int cb = ng * 40 + nt * 8 + 2 * tig;
            zs[rA * 82 + cb] = ac[nt][0];  zs[rA * 82 + cb + 1] = ac[nt][1];
            zs[rB * 82 + cb] = ac[nt][2];  zs[rB * 82 + cb + 1] = ac[nt][3];
        }
        __syncthreads();
        for (int i = tid; i < 360; i += 320) {
            int oc = i / 36, r2 = i - oc * 36, od = r2 / 6, ot = r2 - od * 6;
            float s = __ldg(&b2[oc]);
#pragma unroll
            for (int kt = 0; kt < 7; kt++)
                s += zs[(od * 12 + ot + kt) * 82 + oc * 8 + kt];
            s = fmaxf(s, 0.f);
            g_h2[(size_t)b * 12960 + oc * 1296 + oh * 216 + (ow0 + e) * 36 + od * 6 + ot] = s;
        }
        __syncthreads();
    }
}

// ---------------------------------------------------------------------------
__global__ __launch_bounds__(256)
void linear_kernel(const float* __restrict__ wl, const float* __restrict__ bl,
                   float* __restrict__ out)
{
    const int b = blockIdx.x;
    const float* h = g_h2 + (size_t)b * 12960;
    float s = 0.f;
    for (int i = threadIdx.x; i < 12960; i += 256) s = fmaf(h[i], wl[i], s);
    __shared__ float red[8];
#pragma unroll
    for (int o = 16; o; o >>= 1) s += __shfl_xor_sync(0xFFFFFFFFu, s, o);
    if ((threadIdx.x & 31) == 0) red[threadIdx.x >> 5] = s;
    __syncthreads();
    if (threadIdx.x < 32) {
        s = (threadIdx.x < 8) ? red[threadIdx.x] : 0.f;
#pragma unroll
        for (int o = 4; o; o >>= 1) s += __shfl_xor_sync(0xFFFFFFFFu, s, o);
        if (threadIdx.x == 0) out[b] = 1.f / (1.f + expf(-(s + bl[0])));
    }
}

// ---------------------------------------------------------------------------
extern "C" void kernel_launch(void* const* d_in, const int* in_sizes, int n_in,
                              void* d_out, int out_size)
{
    const float* x    = (const float*)d_in[0];
    const float* w1   = (const float*)d_in[1];
    const float* b1   = (const float*)d_in[2];
    const float* w2   = (const float*)d_in[3];
    const float* b2   = (const float*)d_in[4];
    const float* wlin = (const float*)d_in[5];
    const float* blin = (const float*)d_in[6];
    float* out = (float*)d_out;

    const size_t smem1 = 50816u * 4;   // 203264 B
    const size_t smem2 = 54096u * 4;   // 216384 B
    cudaFuncSetAttribute(conv1_mma, cudaFuncAttributeMaxDynamicSharedMemorySize, (int)smem1);
    cudaFuncSetAttribute(conv2_mma, cudaFuncAttributeMaxDynamicSharedMemorySize, (int)smem2);

    pack_x<<<(NB * 324 * 360 + 255) / 256, 256>>>(x);
    pack_w1<<<14, 256>>>(w1);
    pack_w2<<<135, 256>>>(w2);
    conv1_mma<<<NB * 24, 512, smem1>>>(b1);
    conv2_mma<<<NB * 18, 320, smem2>>>(b2);
    linear_kernel<<<NB, 256>>>(wlin, blin, out);
}

// round 11
// speedup vs baseline: 2.0228x; 1.0513x over previous
#include <cuda_runtime.h>
#include <cuda_fp16.h>
typedef unsigned int u32;
#define NB 128

// ---------------------------------------------------------------------------
// Globals (no cudaMalloc allowed)
// ---------------------------------------------------------------------------
__device__ __align__(16) u32   g_xp[NB * 18 * 18 * 360];          // x split-packed fp16, d-stride 20
__device__ __align__(16) u32   g_h1p[NB * 5 * 12 * 12 * 144];     // conv1 out split-packed fp16
__device__ float               g_h2[NB * 10 * 1296];
__device__ __align__(16) uint2 g_w1p[22 * 4 * 40];                // B1 fp16 fragments
__device__ __align__(16) uint2 g_w2p[108 * 4 * 80];               // B2 fp16 fragments

// ---------------------------------------------------------------------------
__device__ __forceinline__ u32 psh(float v) {   // split-pack: fp16 hi | fp16 lo<<16
    __half h = __float2half_rn(v);
    __half l = __float2half_rn(v - __half2float(h));
    return (u32)__half_as_ushort(h) | ((u32)__half_as_ushort(l) << 16);
}
__device__ __forceinline__ u32 ph2(float v0, float v1) {
    return (u32)__half_as_ushort(__float2half_rn(v0))
         | ((u32)__half_as_ushort(__float2half_rn(v1)) << 16);
}
__device__ __forceinline__ void mma16816(float* c, const u32* a, u32 b0, u32 b1) {
    asm volatile("mma.sync.aligned.m16n8k16.row.col.f32.f16.f16.f32 "
        "{%0,%1,%2,%3},{%4,%5,%6,%7},{%8,%9},{%0,%1,%2,%3};"
        : "+f"(c[0]), "+f"(c[1]), "+f"(c[2]), "+f"(c[3])
        : "r"(a[0]), "r"(a[1]), "r"(a[2]), "r"(a[3]), "r"(b0), "r"(b1));
}
__device__ __forceinline__ void cp16(u32 dst, const void* src) {
    asm volatile("cp.async.cg.shared.global [%0], [%1], 16;" :: "r"(dst), "l"(src));
}
__device__ __forceinline__ void cp_commit() { asm volatile("cp.async.commit_group;"); }
__device__ __forceinline__ void cp_wait0()  { asm volatile("cp.async.wait_group 0;"); }
__device__ __forceinline__ void cp_wait1()  { asm volatile("cp.async.wait_group 1;"); }

// ---------------------------------------------------------------------------
// pack kernels
// ---------------------------------------------------------------------------
__global__ void pack_x(const float* __restrict__ x) {
    int i = blockIdx.x * 256 + threadIdx.x;
    if (i >= NB * 324 * 360) return;
    int seg = i / 360, r = i % 360, d = r / 20, t = r % 20;
    g_xp[i] = (t < 18) ? psh(x[(size_t)seg * 324 + d * 18 + t]) : 0u;
}
__global__ void pack_w1(const float* __restrict__ w1) {
    int i = blockIdx.x * 256 + threadIdx.x;
    if (i >= 3520) return;
    int kcti = i / 40, n = i % 40, oc = n >> 3, kt = n & 7;
    int k0 = (kcti >> 2) * 16 + 2 * (kcti & 3);
    float v[4];
#pragma unroll
    for (int j = 0; j < 4; j++) {
        int k = k0 + (j & 1) + (j >> 1) * 8;
        v[j] = (k < 343 && kt < 7) ? w1[oc * 2401 + k * 7 + kt] : 0.f;
    }
    uint2 o; o.x = ph2(v[0], v[1]); o.y = ph2(v[2], v[3]);
    g_w1p[i] = o;
}
__global__ void pack_w2(const float* __restrict__ w2) {
    int i = blockIdx.x * 256 + threadIdx.x;
    if (i >= 34560) return;
    int kcti = i / 80, n = i % 80, oc = n >> 3, kt = n & 7;
    int k0 = (kcti >> 2) * 16 + 2 * (kcti & 3);
    float v[4];
#pragma unroll
    for (int j = 0; j < 4; j++) {
        int k = k0 + (j & 1) + (j >> 1) * 8;
        v[j] = 0.f;
        if (k < 1715 && kt < 7) {
            int ic = k / 343, t3 = k - ic * 343;
            v[j] = w2[(size_t)oc * 12005 + ic * 2401 + t3 * 7 + kt];
        }
    }
    uint2 o; o.x = ph2(v[0], v[1]); o.y = ph2(v[2], v[3]);
    g_w2p[i] = o;
}

// ---------------------------------------------------------------------------
// conv1: CTA=(b, oh, ow-half). 512 thr (16 warps). 3 passes x 2 owl.
// (unchanged from R10 winner)
// ---------------------------------------------------------------------------
__global__ __launch_bounds__(512, 1)
void conv1_mma(const float* __restrict__ b1)
{
    extern __shared__ u32 sm[];
    u32*   xs   = sm;
    u32*   tbl  = sm + 32320;
    uint4* tb4  = (uint4*)tbl;
    uint2* ws2  = (uint2*)(sm + 32672);
    float* zs   = (float*)(sm + 40064);

    const int bid = blockIdx.x;
    const int b = bid / 24, r0 = bid % 24, oh = r0 >> 1, ow0 = (r0 & 1) * 6;
    const int tid = threadIdx.x;

    if (tid < 352) {
        int kc = tid >> 4, tg = (tid >> 2) & 3, q = tid & 3;
        int k = kc * 16 + 2 * tg + (q & 1) + (q >> 1) * 8;
        u32 off = 30240u;
        if (k < 343) {
            int kh = k / 49, rm = k - kh * 49, kw = rm / 7, kd = rm - kw * 7;
            off = (u32)((kh * 12 + kw) * 360 + kd * 20);
        }
        tbl[tid] = off;
    }
    for (int i = tid; i < 3520; i += 512) ws2[(i / 40) * 42 + i % 40] = g_w1p[i];
    for (int i = tid; i < 2080; i += 512) xs[30240 + i] = 0u;
    const u32* xb = g_xp + (((size_t)b * 18 + oh) * 18 + ow0) * 360;
    for (int j = tid; j < 7560; j += 512) {
        int seg = j / 90, off = j % 90;
        *(uint4*)&xs[seg * 360 + off * 4] =
            *(const uint4*)(xb + ((size_t)(seg / 12) * 18 + seg % 12) * 360 + off * 4);
    }
    __syncthreads();

    const int lane = tid & 31, wid = tid >> 5, gid = lane >> 2, tig = lane & 3;
    const int rA = wid * 16 + gid;

    for (int p = 0; p < 3; p++) {
        const int bA = p * 720 + rA;
        float acc0[5][4], acc1[5][4];
#pragma unroll
        for (int nt = 0; nt < 5; nt++)
#pragma unroll
            for (int q = 0; q < 4; q++) { acc0[nt][q] = 0.f; acc1[nt][q] = 0.f; }

#pragma unroll
        for (int kc = 0; kc < 22; kc++) {
            const uint4 off = tb4[kc * 4 + tig];
            const u32 a0 = off.x + bA, a1 = off.y + bA, a2 = off.z + bA, a3 = off.w + bA;
            u32 pa = xs[a0],      pb = xs[a1];
            u32 pc = xs[a0 + 8],  pd = xs[a1 + 8];
            u32 pe = xs[a2],      pf = xs[a3];
            u32 pg = xs[a2 + 8],  ph = xs[a3 + 8];
            u32 h0[4], l0[4];
            h0[0] = __byte_perm(pa, pb, 0x5410); l0[0] = __byte_perm(pa, pb, 0x7632);
            h0[1] = __byte_perm(pc, pd, 0x5410); l0[1] = __byte_perm(pc, pd, 0x7632);
            h0[2] = __byte_perm(pe, pf, 0x5410); l0[2] = __byte_perm(pe, pf, 0x7632);
            h0[3] = __byte_perm(pg, ph, 0x5410); l0[3] = __byte_perm(pg, ph, 0x7632);
            u32 qa = xs[a0 + 360], qb = xs[a1 + 360];
            u32 qc = xs[a0 + 368], qd = xs[a1 + 368];
            u32 qe = xs[a2 + 360], qf = xs[a3 + 360];
            u32 qg = xs[a2 + 368], qh = xs[a3 + 368];
            u32 h1[4], l1[4];
            h1[0] = __byte_perm(qa, qb, 0x5410); l1[0] = __byte_perm(qa, qb, 0x7632);
            h1[1] = __byte_perm(qc, qd, 0x5410); l1[1] = __byte_perm(qc, qd, 0x7632);
            h1[2] = __byte_perm(qe, qf, 0x5410); l1[2] = __byte_perm(qe, qf, 0x7632);
            h1[3] = __byte_perm(qg, qh, 0x5410); l1[3] = __byte_perm(qg, qh, 0x7632);
#pragma unroll
            for (int nt = 0; nt < 5; nt++) {
                uint2 wv = ws2[(kc * 4 + tig) * 42 + nt * 8 + gid];
                mma16816(acc0[nt], h0, wv.x, wv.y);
                mma16816(acc0[nt], l0, wv.x, wv.y);
                mma16816(acc1[nt], h1, wv.x, wv.y);
                mma16816(acc1[nt], l1, wv.x, wv.y);
            }
        }

#pragma unroll
        for (int e = 0; e < 2; e++) {
            float (*ac)[4] = e ? acc1 : acc0;
            const int owl = 2 * p + e;
#pragma unroll
            for (int nt = 0; nt < 5; nt++) {
                int cb = nt * 8 + 2 * tig;
                zs[rA * 42 + cb]       = ac[nt][0];  zs[rA * 42 + cb + 1]       = ac[nt][1];
                zs[(rA + 8) * 42 + cb] = ac[nt][2];  zs[(rA + 8) * 42 + cb + 1] = ac[nt][3];
            }
            __syncthreads();
            for (int i = tid; i < 720; i += 512) {
                int oc = i / 144, r2 = i - oc * 144, od = r2 / 12, ot = r2 - od * 12;
                float s = __ldg(&b1[oc]);
#pragma unroll
                for (int kt = 0; kt < 7; kt++)
                    s += zs[(od * 20 + ot + kt) * 42 + oc * 8 + kt];
                s = fmaxf(s, 0.f);
                g_h1p[((((size_t)b * 5 + oc) * 12 + oh) * 12 + ow0 + owl) * 144 + od * 12 + ot] = psh(s);
            }
            __syncthreads();
        }
    }
}

// ---------------------------------------------------------------------------
// conv2: CTA=(b, oh, ow-triple). 320 thr (10 warps). 3 ow per CTA.
// xs: [5 ic][7 kh][9 w] x 144 = 45360 u32 (+384 zero pad).
// zs (80x82 f32) ALIASES xs (xs dead after mainloop).
// SMEM (u32): xs[0,45744) | tbl @45744 (1728) | bq @47472 (5248)
//   => 52720 u32 = 210880 B
// ---------------------------------------------------------------------------
__global__ __launch_bounds__(320, 1)
void conv2_mma(const float* __restrict__ b2)
{
    extern __shared__ u32 sm2[];
    u32*   xs   = sm2;
    u32*   tbl  = sm2 + 45744;
    uint4* tb4  = (uint4*)tbl;
    uint2* bq   = (uint2*)(sm2 + 47472);
    float* zs   = (float*)sm2;            // aliases xs after mainloop

    const int bid = blockIdx.x;
    const int b = bid / 12, r0 = bid % 12;
    const int oh = r0 / 2, ow0 = (r0 % 2) * 3;
    const int tid = threadIdx.x;
    const u32 bq_s = (u32)__cvta_generic_to_shared(bq);

    // prologue: B chunk 0 -> buf 0
#pragma unroll
    for (int s = 0; s < 2; s++) {
        int j = tid + s * 320;
        int r = j / 40, cp = j % 40;
        cp16(bq_s + (u32)(r * 82 + 2 * cp) * 8, &g_w2p[r * 80 + 2 * cp]);
    }
    cp_commit();

    // offset table: seg' = (ic*7+kh)*9 + kw, off = seg'*144 + kd*12
    for (int i = tid; i < 1728; i += 320) {
        int kc = i >> 4, tg = (i >> 2) & 3, q = i & 3;
        int k = kc * 16 + 2 * tg + (q & 1) + (q >> 1) * 8;
        u32 off = 45360u;
        if (k < 1715) {
            int ic = k / 343, rm = k - ic * 343;
            int kh = rm / 49, rm2 = rm - kh * 49;
            int kw = rm2 / 7, kd = rm2 - kw * 7;
            off = (u32)(((ic * 7 + kh) * 9 + kw) * 144 + kd * 12);
        }
        tbl[i] = off;
    }
    for (int i = tid; i < 384; i += 320) xs[45360 + i] = 0u;
    // stage xs: 315 segs x 36 uint4
    for (int j = tid; j < 11340; j += 320) {
        int seg = j / 36, off = j % 36;
        int ic = seg / 63, r3 = seg - ic * 63;
        int kh = r3 / 9, w = r3 - kh * 9;
        *(uint4*)&xs[seg * 144 + off * 4] =
            *(const uint4*)(g_h1p + ((((size_t)b * 5 + ic) * 12 + oh + kh) * 12 + ow0 + w) * 144 + off * 4);
    }

    const int lane = tid & 31, wid = tid >> 5, gid = lane >> 2, tig = lane & 3;
    const int mg = wid % 5, ng = wid / 5;
    const int rA = mg * 16 + gid, rB = rA + 8;

    float acc[3][5][4];
#pragma unroll
    for (int e = 0; e < 3; e++)
#pragma unroll
        for (int nt = 0; nt < 5; nt++)
#pragma unroll
            for (int q = 0; q < 4; q++) acc[e][nt][q] = 0.f;

    for (int ch = 0; ch < 27; ch++) {
        const int buf = ch & 1;
        if (ch < 26) {
            const int base = (ch + 1) * 16;
#pragma unroll
            for (int s = 0; s < 2; s++) {
                int j = tid + s * 320;
                int r = j / 40, cp = j % 40;
                cp16(bq_s + (u32)(((buf ^ 1) * 16 + r) * 82 + 2 * cp) * 8,
                     &g_w2p[(base + r) * 80 + 2 * cp]);
            }
            cp_commit();
            cp_wait1();
        } else {
            cp_wait0();
        }
        __syncthreads();

#pragma unroll
        for (int kk = 0; kk < 4; kk++) {
            const uint4 off = tb4[(ch * 4 + kk) * 4 + tig];
            // load B fragments once for this kk
            uint2 wv[5];
#pragma unroll
            for (int nt = 0; nt < 5; nt++)
                wv[nt] = bq[(buf * 16 + kk * 4 + tig) * 82 + ng * 40 + nt * 8 + gid];
#pragma unroll
            for (int e = 0; e < 3; e++) {
                const u32 sh = e * 144;
                u32 pa = xs[off.x + sh + rA], pb = xs[off.y + sh + rA];
                u32 pc = xs[off.x + sh + rB], pd = xs[off.y + sh + rB];
                u32 pe = xs[off.z + sh + rA], pf = xs[off.w + sh + rA];
                u32 pg = xs[off.z + sh + rB], ph = xs[off.w + sh + rB];
                u32 hh[4], ll[4];
                hh[0] = __byte_perm(pa, pb, 0x5410); ll[0] = __byte_perm(pa, pb, 0x7632);
                hh[1] = __byte_perm(pc, pd, 0x5410); ll[1] = __byte_perm(pc, pd, 0x7632);
                hh[2] = __byte_perm(pe, pf, 0x5410); ll[2] = __byte_perm(pe, pf, 0x7632);
                hh[3] = __byte_perm(pg, ph, 0x5410); ll[3] = __byte_perm(pg, ph, 0x7632);
#pragma unroll
                for (int nt = 0; nt < 5; nt++) {
                    mma16816(acc[e][nt], hh, wv[nt].x, wv[nt].y);
                    mma16816(acc[e][nt], ll, wv[nt].x, wv[nt].y);
                }
            }
        }
        __syncthreads();
    }

    // epilogue: zs aliases xs (all xs reads complete after final barrier)
#pragma unroll
    for (int e = 0; e < 3; e++) {
#pragma unroll
        for (int nt = 0; nt < 5; nt++) {
            int cb = ng * 40 + nt * 8 + 2 * tig;
            zs[rA * 82 + cb] = acc[e][nt][0];  zs[rA * 82 + cb + 1] = acc[e][nt][1];
            zs[rB * 82 + cb] = acc[e][nt][2];  zs[rB * 82 + cb + 1] = acc[e][nt][3];
        }
        __syncthreads();
        for (int i = tid; i < 360; i += 320) {
            int oc = i / 36, r2 = i - oc * 36, od = r2 / 6, ot = r2 - od * 6;
            float s = __ldg(&b2[oc]);
#pragma unroll
            for (int kt = 0; kt < 7; kt++)
                s += zs[(od * 12 + ot + kt) * 82 + oc * 8 + kt];
            s = fmaxf(s, 0.f);
            g_h2[(size_t)b * 12960 + oc * 1296 + oh * 216 + (ow0 + e) * 36 + od * 6 + ot] = s;
        }
        __syncthreads();
    }
}

// ---------------------------------------------------------------------------
__global__ __launch_bounds__(256)
void linear_kernel(const float* __restrict__ wl, const float* __restrict__ bl,
                   float* __restrict__ out)
{
    const int b = blockIdx.x;
    const float* h = g_h2 + (size_t)b * 12960;
    float s = 0.f;
    for (int i = threadIdx.x; i < 12960; i += 256) s = fmaf(h[i], wl[i], s);
    __shared__ float red[8];
#pragma unroll
    for (int o = 16; o; o >>= 1) s += __shfl_xor_sync(0xFFFFFFFFu, s, o);
    if ((threadIdx.x & 31) == 0) red[threadIdx.x >> 5] = s;
    __syncthreads();
    if (threadIdx.x < 32) {
        s = (threadIdx.x < 8) ? red[threadIdx.x] : 0.f;
#pragma unroll
        for (int o = 4; o; o >>= 1) s += __shfl_xor_sync(0xFFFFFFFFu, s, o);
        if (threadIdx.x == 0) out[b] = 1.f / (1.f + expf(-(s + bl[0])));
    }
}

// ---------------------------------------------------------------------------
extern "C" void kernel_launch(void* const* d_in, const int* in_sizes, int n_in,
                              void* d_out, int out_size)
{
    const float* x    = (const float*)d_in[0];
    const float* w1   = (const float*)d_in[1];
    const float* b1   = (const float*)d_in[2];
    const float* w2   = (const float*)d_in[3];
    const float* b2   = (const float*)d_in[4];
    const float* wlin = (const float*)d_in[5];
    const float* blin = (const float*)d_in[6];
    float* out = (float*)d_out;

    const size_t smem1 = 50816u * 4;   // 203264 B
    const size_t smem2 = 52720u * 4;   // 210880 B
    cudaFuncSetAttribute(conv1_mma, cudaFuncAttributeMaxDynamicSharedMemorySize, (int)smem1);
    cudaFuncSetAttribute(conv2_mma, cudaFuncAttributeMaxDynamicSharedMemorySize, (int)smem2);

    pack_x<<<(NB * 324 * 360 + 255) / 256, 256>>>(x);
    pack_w1<<<14, 256>>>(w1);
    pack_w2<<<135, 256>>>(w2);
    conv1_mma<<<NB * 24, 512, smem1>>>(b1);
    conv2_mma<<<NB * 12, 320, smem2>>>(b2);
    linear_kernel<<<NB, 256>>>(wlin, blin, out);
}

// round 12
// speedup vs baseline: 2.0923x; 1.0344x over previous
#include <cuda_runtime.h>
#include <cuda_fp16.h>
typedef unsigned int u32;
#define NB 128

// ---------------------------------------------------------------------------
// Globals (no cudaMalloc allowed)
// ---------------------------------------------------------------------------
__device__ __align__(16) u32   g_xp[NB * 18 * 18 * 324];          // x split-packed fp16, dense [h][w][d][t]
__device__ __align__(16) u32   g_h1p[NB * 5 * 12 * 12 * 144];     // conv1 out split-packed fp16
__device__ float               g_h2[NB * 10 * 1296];
__device__ __align__(16) uint2 g_w1p[22 * 4 * 40];                // B1 fp16 fragments
__device__ __align__(16) uint2 g_w2p[108 * 4 * 80];               // B2 fp16 fragments

// ---------------------------------------------------------------------------
__device__ __forceinline__ u32 psh(float v) {   // split-pack: fp16 hi | fp16 lo<<16
    __half h = __float2half_rn(v);
    __half l = __float2half_rn(v - __half2float(h));
    return (u32)__half_as_ushort(h) | ((u32)__half_as_ushort(l) << 16);
}
__device__ __forceinline__ u32 ph2(float v0, float v1) {
    return (u32)__half_as_ushort(__float2half_rn(v0))
         | ((u32)__half_as_ushort(__float2half_rn(v1)) << 16);
}
__device__ __forceinline__ void mma16816(float* c, const u32* a, u32 b0, u32 b1) {
    asm volatile("mma.sync.aligned.m16n8k16.row.col.f32.f16.f16.f32 "
        "{%0,%1,%2,%3},{%4,%5,%6,%7},{%8,%9},{%0,%1,%2,%3};"
        : "+f"(c[0]), "+f"(c[1]), "+f"(c[2]), "+f"(c[3])
        : "r"(a[0]), "r"(a[1]), "r"(a[2]), "r"(a[3]), "r"(b0), "r"(b1));
}
__device__ __forceinline__ void cp16(u32 dst, const void* src) {
    asm volatile("cp.async.cg.shared.global [%0], [%1], 16;" :: "r"(dst), "l"(src));
}
__device__ __forceinline__ void cp_commit() { asm volatile("cp.async.commit_group;"); }
__device__ __forceinline__ void cp_wait0()  { asm volatile("cp.async.wait_group 0;"); }
__device__ __forceinline__ void cp_wait1()  { asm volatile("cp.async.wait_group 1;"); }

// ---------------------------------------------------------------------------
// pack kernels
// ---------------------------------------------------------------------------
__global__ void pack_x(const float* __restrict__ x) {
    int i = blockIdx.x * 256 + threadIdx.x;
    if (i >= NB * 104976) return;
    g_xp[i] = psh(x[i]);
}
__global__ void pack_w1(const float* __restrict__ w1) {
    int i = blockIdx.x * 256 + threadIdx.x;
    if (i >= 3520) return;
    int kcti = i / 40, n = i % 40, oc = n >> 3, kt = n & 7;
    int k0 = (kcti >> 2) * 16 + 2 * (kcti & 3);
    float v[4];
#pragma unroll
    for (int j = 0; j < 4; j++) {
        int k = k0 + (j & 1) + (j >> 1) * 8;
        v[j] = (k < 343 && kt < 7) ? w1[oc * 2401 + k * 7 + kt] : 0.f;
    }
    uint2 o; o.x = ph2(v[0], v[1]); o.y = ph2(v[2], v[3]);
    g_w1p[i] = o;
}
__global__ void pack_w2(const float* __restrict__ w2) {
    int i = blockIdx.x * 256 + threadIdx.x;
    if (i >= 34560) return;
    int kcti = i / 80, n = i % 80, oc = n >> 3, kt = n & 7;
    int k0 = (kcti >> 2) * 16 + 2 * (kcti & 3);
    float v[4];
#pragma unroll
    for (int j = 0; j < 4; j++) {
        int k = k0 + (j & 1) + (j >> 1) * 8;
        v[j] = 0.f;
        if (k < 1715 && kt < 7) {
            int ic = k / 343, t3 = k - ic * 343;
            v[j] = w2[(size_t)oc * 12005 + ic * 2401 + t3 * 7 + kt];
        }
    }
    uint2 o; o.x = ph2(v[0], v[1]); o.y = ph2(v[2], v[3]);
    g_w2p[i] = o;
}

// ---------------------------------------------------------------------------
// conv1: CTA=(b, oh, ow-half). 448 thr (14 warps, 1 m-tile each).
// Dense stride-18 geometry: m = od*18 + t (216 dense, M=224 = 14 tiles),
// A addr = seg*324 + kd*18 + owl*324 + m (affine). 2 passes x 3 owl,
// B fragments loaded once per kc feed 30 MMAs.
// SMEM (u32): xs[0,29072) (27216 data + 1856 zero pad) | tbl @29072 (352)
//             | ws2 @29424 (7392) | zs @36816 (9408)  => 46224 u32 = 184896 B
// ---------------------------------------------------------------------------
__global__ __launch_bounds__(448, 1)
void conv1_mma(const float* __restrict__ b1)
{
    extern __shared__ u32 sm[];
    u32*   xs   = sm;
    u32*   tbl  = sm + 29072;
    uint4* tb4  = (uint4*)tbl;
    uint2* ws2  = (uint2*)(sm + 29424);
    float* zs   = (float*)(sm + 36816);

    const int bid = blockIdx.x;
    const int b = bid / 24, r0 = bid % 24, oh = r0 >> 1, ow0 = (r0 & 1) * 6;
    const int tid = threadIdx.x;

    // offset table: tbl[kc*16 + tig*4 + q]
    if (tid < 352) {
        int kc = tid >> 4, tg = (tid >> 2) & 3, q = tid & 3;
        int k = kc * 16 + 2 * tg + (q & 1) + (q >> 1) * 8;
        u32 off = 27216u;                       // OOB -> zero pad
        if (k < 343) {
            int kh = k / 49, rm = k - kh * 49, kw = rm / 7, kd = rm - kw * 7;
            off = (u32)((kh * 12 + kw) * 324 + kd * 18);
        }
        tbl[tid] = off;
    }
    for (int i = tid; i < 3520; i += 448) ws2[(i / 40) * 42 + i % 40] = g_w1p[i];
    for (int i = tid; i < 1856; i += 448) xs[27216 + i] = 0u;
    const u32* xb = g_xp + (((size_t)b * 18 + oh) * 18 + ow0) * 324;
    for (int j = tid; j < 6804; j += 448) {
        int seg = j / 81, off = j % 81;
        *(uint4*)&xs[seg * 324 + off * 4] =
            *(const uint4*)(xb + ((size_t)(seg / 12) * 18 + seg % 12) * 324 + off * 4);
    }
    __syncthreads();

    const int lane = tid & 31, wid = tid >> 5, gid = lane >> 2, tig = lane & 3;
    const int rA = wid * 16 + gid;

    for (int p = 0; p < 2; p++) {
        const int bA = p * 972 + rA;             // owl0 = 3p
        float acc[3][5][4];
#pragma unroll
        for (int e = 0; e < 3; e++)
#pragma unroll
            for (int nt = 0; nt < 5; nt++)
#pragma unroll
                for (int q = 0; q < 4; q++) acc[e][nt][q] = 0.f;

#pragma unroll
        for (int kc = 0; kc < 22; kc++) {
            const uint4 off = tb4[kc * 4 + tig];
            uint2 wv[5];
#pragma unroll
            for (int nt = 0; nt < 5; nt++)
                wv[nt] = ws2[(kc * 4 + tig) * 42 + nt * 8 + gid];
#pragma unroll
            for (int e = 0; e < 3; e++) {
                const u32 sh = e * 324 + bA;
                u32 pa = xs[off.x + sh],     pb = xs[off.y + sh];
                u32 pc = xs[off.x + sh + 8], pd = xs[off.y + sh + 8];
                u32 pe = xs[off.z + sh],     pf = xs[off.w + sh];
                u32 pg = xs[off.z + sh + 8], ph = xs[off.w + sh + 8];
                u32 hh[4], ll[4];
                hh[0] = __byte_perm(pa, pb, 0x5410); ll[0] = __byte_perm(pa, pb, 0x7632);
                hh[1] = __byte_perm(pc, pd, 0x5410); ll[1] = __byte_perm(pc, pd, 0x7632);
                hh[2] = __byte_perm(pe, pf, 0x5410); ll[2] = __byte_perm(pe, pf, 0x7632);
                hh[3] = __byte_perm(pg, ph, 0x5410); ll[3] = __byte_perm(pg, ph, 0x7632);
#pragma unroll
                for (int nt = 0; nt < 5; nt++) {
                    mma16816(acc[e][nt], hh, wv[nt].x, wv[nt].y);
                    mma16816(acc[e][nt], ll, wv[nt].x, wv[nt].y);
                }
            }
        }

        // three epilogues (zs single-buffered)
#pragma unroll
        for (int e = 0; e < 3; e++) {
            const int owl = 3 * p + e;
#pragma unroll
            for (int nt = 0; nt < 5; nt++) {
                int cb = nt * 8 + 2 * tig;
                zs[rA * 42 + cb]       = acc[e][nt][0];  zs[rA * 42 + cb + 1]       = acc[e][nt][1];
                zs[(rA + 8) * 42 + cb] = acc[e][nt][2];  zs[(rA + 8) * 42 + cb + 1] = acc[e][nt][3];
            }
            __syncthreads();
            for (int i = tid; i < 720; i += 448) {
                int oc = i / 144, r2 = i - oc * 144, od = r2 / 12, ot = r2 - od * 12;
                float s = __ldg(&b1[oc]);
#pragma unroll
                for (int kt = 0; kt < 7; kt++)
                    s += zs[(od * 18 + ot + kt) * 42 + oc * 8 + kt];
                s = fmaxf(s, 0.f);
                g_h1p[((((size_t)b * 5 + oc) * 12 + oh) * 12 + ow0 + owl) * 144 + od * 12 + ot] = psh(s);
            }
            __syncthreads();
        }
    }
}

// ---------------------------------------------------------------------------
// conv2: CTA=(b, oh, ow-triple). 320 thr (10 warps). 3 ow per CTA.
// (unchanged from R11 winner)
// SMEM (u32): xs[0,45744) | tbl @45744 (1728) | bq @47472 (5248)
//   => 52720 u32 = 210880 B ; zs aliases xs after mainloop.
// ---------------------------------------------------------------------------
__global__ __launch_bounds__(320, 1)
void conv2_mma(const float* __restrict__ b2)
{
    extern __shared__ u32 sm2[];
    u32*   xs   = sm2;
    u32*   tbl  = sm2 + 45744;
    uint4* tb4  = (uint4*)tbl;
    uint2* bq   = (uint2*)(sm2 + 47472);
    float* zs   = (float*)sm2;            // aliases xs after mainloop

    const int bid = blockIdx.x;
    const int b = bid / 12, r0 = bid % 12;
    const int oh = r0 / 2, ow0 = (r0 % 2) * 3;
    const int tid = threadIdx.x;
    const u32 bq_s = (u32)__cvta_generic_to_shared(bq);

    // prologue: B chunk 0 -> buf 0
#pragma unroll
    for (int s = 0; s < 2; s++) {
        int j = tid + s * 320;
        int r = j / 40, cp = j % 40;
        cp16(bq_s + (u32)(r * 82 + 2 * cp) * 8, &g_w2p[r * 80 + 2 * cp]);
    }
    cp_commit();

    // offset table: seg' = (ic*7+kh)*9 + kw, off = seg'*144 + kd*12
    for (int i = tid; i < 1728; i += 320) {
        int kc = i >> 4, tg = (i >> 2) & 3, q = i & 3;
        int k = kc * 16 + 2 * tg + (q & 1) + (q >> 1) * 8;
        u32 off = 45360u;
        if (k < 1715) {
            int ic = k / 343, rm = k - ic * 343;
            int kh = rm / 49, rm2 = rm - kh * 49;
            int kw = rm2 / 7, kd = rm2 - kw * 7;
            off = (u32)(((ic * 7 + kh) * 9 + kw) * 144 + kd * 12);
        }
        tbl[i] = off;
    }
    for (int i = tid; i < 384; i += 320) xs[45360 + i] = 0u;
    // stage xs: 315 segs x 36 uint4
    for (int j = tid; j < 11340; j += 320) {
        int seg = j / 36, off = j % 36;
        int ic = seg / 63, r3 = seg - ic * 63;
        int kh = r3 / 9, w = r3 - kh * 9;
        *(uint4*)&xs[seg * 144 + off * 4] =
            *(const uint4*)(g_h1p + ((((size_t)b * 5 + ic) * 12 + oh + kh) * 12 + ow0 + w) * 144 + off * 4);
    }

    const int lane = tid & 31, wid = tid >> 5, gid = lane >> 2, tig = lane & 3;
    const int mg = wid % 5, ng = wid / 5;
    const int rA = mg * 16 + gid, rB = rA + 8;

    float acc[3][5][4];
#pragma unroll
    for (int e = 0; e < 3; e++)
#pragma unroll
        for (int nt = 0; nt < 5; nt++)
#pragma unroll
            for (int q = 0; q < 4; q++) acc[e][nt][q] = 0.f;

    for (int ch = 0; ch < 27; ch++) {
        const int buf = ch & 1;
        if (ch < 26) {
            const int base = (ch + 1) * 16;
#pragma unroll
            for (int s = 0; s < 2; s++) {
                int j = tid + s * 320;
                int r = j / 40, cp = j % 40;
                cp16(bq_s + (u32)(((buf ^ 1) * 16 + r) * 82 + 2 * cp) * 8,
                     &g_w2p[(base + r) * 80 + 2 * cp]);
            }
            cp_commit();
            cp_wait1();
        } else {
            cp_wait0();
        }
        __syncthreads();

#pragma unroll
        for (int kk = 0; kk < 4; kk++) {
            const uint4 off = tb4[(ch * 4 + kk) * 4 + tig];
            uint2 wv[5];
#pragma unroll
            for (int nt = 0; nt < 5; nt++)
                wv[nt] = bq[(buf * 16 + kk * 4 + tig) * 82 + ng * 40 + nt * 8 + gid];
#pragma unroll
            for (int e = 0; e < 3; e++) {
                const u32 sh = e * 144;
                u32 pa = xs[off.x + sh + rA], pb = xs[off.y + sh + rA];
                u32 pc = xs[off.x + sh + rB], pd = xs[off.y + sh + rB];
                u32 pe = xs[off.z + sh + rA], pf = xs[off.w + sh + rA];
                u32 pg = xs[off.z + sh + rB], ph = xs[off.w + sh + rB];
                u32 hh[4], ll[4];
                hh[0] = __byte_perm(pa, pb, 0x5410); ll[0] = __byte_perm(pa, pb, 0x7632);
                hh[1] = __byte_perm(pc, pd, 0x5410); ll[1] = __byte_perm(pc, pd, 0x7632);
                hh[2] = __byte_perm(pe, pf, 0x5410); ll[2] = __byte_perm(pe, pf, 0x7632);
                hh[3] = __byte_perm(pg, ph, 0x5410); ll[3] = __byte_perm(pg, ph, 0x7632);
#pragma unroll
                for (int nt = 0; nt < 5; nt++) {
                    mma16816(acc[e][nt], hh, wv[nt].x, wv[nt].y);
                    mma16816(acc[e][nt], ll, wv[nt].x, wv[nt].y);
                }
            }
        }
        __syncthreads();
    }

    // epilogue: zs aliases xs (all xs reads complete after final barrier)
#pragma unroll
    for (int e = 0; e < 3; e++) {
#pragma unroll
        for (int nt = 0; nt < 5; nt++) {
            int cb = ng * 40 + nt * 8 + 2 * tig;
            zs[rA * 82 + cb] = acc[e][nt][0];  zs[rA * 82 + cb + 1] = acc[e][nt][1];
            zs[rB * 82 + cb] = acc[e][nt][2];  zs[rB * 82 + cb + 1] = acc[e][nt][3];
        }
        __syncthreads();
        for (int i = tid; i < 360; i += 320) {
            int oc = i / 36, r2 = i - oc * 36, od = r2 / 6, ot = r2 - od * 6;
            float s = __ldg(&b2[oc]);
#pragma unroll
            for (int kt = 0; kt < 7; kt++)
                s += zs[(od * 12 + ot + kt) * 82 + oc * 8 + kt];
            s = fmaxf(s, 0.f);
            g_h2[(size_t)b * 12960 + oc * 1296 + oh * 216 + (ow0 + e) * 36 + od * 6 + ot] = s;
        }
        __syncthreads();
    }
}

// ---------------------------------------------------------------------------
__global__ __launch_bounds__(256)
void linear_kernel(const float* __restrict__ wl, const float* __restrict__ bl,
                   float* __restrict__ out)
{
    const int b = blockIdx.x;
    const float* h = g_h2 + (size_t)b * 12960;
    float s = 0.f;
    for (int i = threadIdx.x; i < 12960; i += 256) s = fmaf(h[i], wl[i], s);
    __shared__ float red[8];
#pragma unroll
    for (int o = 16; o; o >>= 1) s += __shfl_xor_sync(0xFFFFFFFFu, s, o);
    if ((threadIdx.x & 31) == 0) red[threadIdx.x >> 5] = s;
    __syncthreads();
    if (threadIdx.x < 32) {
        s = (threadIdx.x < 8) ? red[threadIdx.x] : 0.f;
#pragma unroll
        for (int o = 4; o; o >>= 1) s += __shfl_xor_sync(0xFFFFFFFFu, s, o);
        if (threadIdx.x == 0) out[b] = 1.f / (1.f + expf(-(s + bl[0])));
    }
}

// ---------------------------------------------------------------------------
extern "C" void kernel_launch(void* const* d_in, const int* in_sizes, int n_in,
                              void* d_out, int out_size)
{
    const float* x    = (const float*)d_in[0];
    const float* w1   = (const float*)d_in[1];
    const float* b1   = (const float*)d_in[2];
    const float* w2   = (const float*)d_in[3];
    const float* b2   = (const float*)d_in[4];
    const float* wlin = (const float*)d_in[5];
    const float* blin = (const float*)d_in[6];
    float* out = (float*)d_out;

    const size_t smem1 = 46224u * 4;   // 184896 B
    const size_t smem2 = 52720u * 4;   // 210880 B
    cudaFuncSetAttribute(conv1_mma, cudaFuncAttributeMaxDynamicSharedMemorySize, (int)smem1);
    cudaFuncSetAttribute(conv2_mma, cudaFuncAttributeMaxDynamicSharedMemorySize, (int)smem2);

    pack_x<<<(NB * 104976 + 255) / 256, 256>>>(x);
    pack_w1<<<14, 256>>>(w1);
    pack_w2<<<135, 256>>>(w2);
    conv1_mma<<<NB * 24, 448, smem1>>>(b1);
    conv2_mma<<<NB * 12, 320, smem2>>>(b2);
    linear_kernel<<<NB, 256>>>(wlin, blin, out);
}

// round 13
// speedup vs baseline: 2.1039x; 1.0056x over previous
#include <cuda_runtime.h>
#include <cuda_fp16.h>
typedef unsigned int u32;
#define NB 128

// ---------------------------------------------------------------------------
// Globals (no cudaMalloc allowed)
// ---------------------------------------------------------------------------
__device__ __align__(16) u32   g_xp[NB * 18 * 18 * 324];          // x split-packed fp16, dense [h][w][d][t]
__device__ __align__(16) u32   g_h1p[NB * 5 * 12 * 12 * 144];     // conv1 out split-packed fp16
__device__ float               g_h2[NB * 10 * 1296];
__device__ __align__(16) uint2 g_w1p[22 * 4 * 40];                // B1 fp16 fragments
__device__ __align__(16) uint2 g_w2p[108 * 4 * 80];               // B2 fp16 fragments

// ---------------------------------------------------------------------------
__device__ __forceinline__ u32 psh(float v) {   // split-pack: fp16 hi | fp16 lo<<16
    __half h = __float2half_rn(v);
    __half l = __float2half_rn(v - __half2float(h));
    return (u32)__half_as_ushort(h) | ((u32)__half_as_ushort(l) << 16);
}
__device__ __forceinline__ u32 ph2(float v0, float v1) {
    return (u32)__half_as_ushort(__float2half_rn(v0))
         | ((u32)__half_as_ushort(__float2half_rn(v1)) << 16);
}
__device__ __forceinline__ void mma16816(float* c, const u32* a, u32 b0, u32 b1) {
    asm volatile("mma.sync.aligned.m16n8k16.row.col.f32.f16.f16.f32 "
        "{%0,%1,%2,%3},{%4,%5,%6,%7},{%8,%9},{%0,%1,%2,%3};"
        : "+f"(c[0]), "+f"(c[1]), "+f"(c[2]), "+f"(c[3])
        : "r"(a[0]), "r"(a[1]), "r"(a[2]), "r"(a[3]), "r"(b0), "r"(b1));
}

// ---------------------------------------------------------------------------
// pack kernels
// ---------------------------------------------------------------------------
__global__ void pack_x(const float* __restrict__ x) {
    int i = blockIdx.x * 256 + threadIdx.x;
    if (i >= NB * 104976) return;
    g_xp[i] = psh(x[i]);
}
__global__ void pack_w1(const float* __restrict__ w1) {
    int i = blockIdx.x * 256 + threadIdx.x;
    if (i >= 3520) return;
    int kcti = i / 40, n = i % 40, oc = n >> 3, kt = n & 7;
    int k0 = (kcti >> 2) * 16 + 2 * (kcti & 3);
    float v[4];
#pragma unroll
    for (int j = 0; j < 4; j++) {
        int k = k0 + (j & 1) + (j >> 1) * 8;
        v[j] = (k < 343 && kt < 7) ? w1[oc * 2401 + k * 7 + kt] : 0.f;
    }
    uint2 o; o.x = ph2(v[0], v[1]); o.y = ph2(v[2], v[3]);
    g_w1p[i] = o;
}
__global__ void pack_w2(const float* __restrict__ w2) {
    int i = blockIdx.x * 256 + threadIdx.x;
    if (i >= 34560) return;
    int kcti = i / 80, n = i % 80, oc = n >> 3, kt = n & 7;
    int k0 = (kcti >> 2) * 16 + 2 * (kcti & 3);
    float v[4];
#pragma unroll
    for (int j = 0; j < 4; j++) {
        int k = k0 + (j & 1) + (j >> 1) * 8;
        v[j] = 0.f;
        if (k < 1715 && kt < 7) {
            int ic = k / 343, t3 = k - ic * 343;
            v[j] = w2[(size_t)oc * 12005 + ic * 2401 + t3 * 7 + kt];
        }
    }
    uint2 o; o.x = ph2(v[0], v[1]); o.y = ph2(v[2], v[3]);
    g_w2p[i] = o;
}

// ---------------------------------------------------------------------------
// conv1: CTA=(b, oh, ow-half). 448 thr (14 warps, 1 m-tile each).
// Dense stride-18, 2 passes x 3 owl. (unchanged from R12 winner)
// SMEM (u32): xs[0,29072) | tbl @29072 (352) | ws2 @29424 (7392) | zs @36816 (9408)
// ---------------------------------------------------------------------------
__global__ __launch_bounds__(448, 1)
void conv1_mma(const float* __restrict__ b1)
{
    extern __shared__ u32 sm[];
    u32*   xs   = sm;
    u32*   tbl  = sm + 29072;
    uint4* tb4  = (uint4*)tbl;
    uint2* ws2  = (uint2*)(sm + 29424);
    float* zs   = (float*)(sm + 36816);

    const int bid = blockIdx.x;
    const int b = bid / 24, r0 = bid % 24, oh = r0 >> 1, ow0 = (r0 & 1) * 6;
    const int tid = threadIdx.x;

    if (tid < 352) {
        int kc = tid >> 4, tg = (tid >> 2) & 3, q = tid & 3;
        int k = kc * 16 + 2 * tg + (q & 1) + (q >> 1) * 8;
        u32 off = 27216u;
        if (k < 343) {
            int kh = k / 49, rm = k - kh * 49, kw = rm / 7, kd = rm - kw * 7;
            off = (u32)((kh * 12 + kw) * 324 + kd * 18);
        }
        tbl[tid] = off;
    }
    for (int i = tid; i < 3520; i += 448) ws2[(i / 40) * 42 + i % 40] = g_w1p[i];
    for (int i = tid; i < 1856; i += 448) xs[27216 + i] = 0u;
    const u32* xb = g_xp + (((size_t)b * 18 + oh) * 18 + ow0) * 324;
    for (int j = tid; j < 6804; j += 448) {
        int seg = j / 81, off = j % 81;
        *(uint4*)&xs[seg * 324 + off * 4] =
            *(const uint4*)(xb + ((size_t)(seg / 12) * 18 + seg % 12) * 324 + off * 4);
    }
    __syncthreads();

    const int lane = tid & 31, wid = tid >> 5, gid = lane >> 2, tig = lane & 3;
    const int rA = wid * 16 + gid;

    for (int p = 0; p < 2; p++) {
        const int bA = p * 972 + rA;             // owl0 = 3p
        float acc[3][5][4];
#pragma unroll
        for (int e = 0; e < 3; e++)
#pragma unroll
            for (int nt = 0; nt < 5; nt++)
#pragma unroll
                for (int q = 0; q < 4; q++) acc[e][nt][q] = 0.f;

#pragma unroll
        for (int kc = 0; kc < 22; kc++) {
            const uint4 off = tb4[kc * 4 + tig];
            uint2 wv[5];
#pragma unroll
            for (int nt = 0; nt < 5; nt++)
                wv[nt] = ws2[(kc * 4 + tig) * 42 + nt * 8 + gid];
#pragma unroll
            for (int e = 0; e < 3; e++) {
                const u32 sh = e * 324 + bA;
                u32 pa = xs[off.x + sh],     pb = xs[off.y + sh];
                u32 pc = xs[off.x + sh + 8], pd = xs[off.y + sh + 8];
                u32 pe = xs[off.z + sh],     pf = xs[off.w + sh];
                u32 pg = xs[off.z + sh + 8], ph = xs[off.w + sh + 8];
                u32 hh[4], ll[4];
                hh[0] = __byte_perm(pa, pb, 0x5410); ll[0] = __byte_perm(pa, pb, 0x7632);
                hh[1] = __byte_perm(pc, pd, 0x5410); ll[1] = __byte_perm(pc, pd, 0x7632);
                hh[2] = __byte_perm(pe, pf, 0x5410); ll[2] = __byte_perm(pe, pf, 0x7632);
                hh[3] = __byte_perm(pg, ph, 0x5410); ll[3] = __byte_perm(pg, ph, 0x7632);
#pragma unroll
                for (int nt = 0; nt < 5; nt++) {
                    mma16816(acc[e][nt], hh, wv[nt].x, wv[nt].y);
                    mma16816(acc[e][nt], ll, wv[nt].x, wv[nt].y);
                }
            }
        }

#pragma unroll
        for (int e = 0; e < 3; e++) {
            const int owl = 3 * p + e;
#pragma unroll
            for (int nt = 0; nt < 5; nt++) {
                int cb = nt * 8 + 2 * tig;
                zs[rA * 42 + cb]       = acc[e][nt][0];  zs[rA * 42 + cb + 1]       = acc[e][nt][1];
                zs[(rA + 8) * 42 + cb] = acc[e][nt][2];  zs[(rA + 8) * 42 + cb + 1] = acc[e][nt][3];
            }
            __syncthreads();
            for (int i = tid; i < 720; i += 448) {
                int oc = i / 144, r2 = i - oc * 144, od = r2 / 12, ot = r2 - od * 12;
                float s = __ldg(&b1[oc]);
#pragma unroll
                for (int kt = 0; kt < 7; kt++)
                    s += zs[(od * 18 + ot + kt) * 42 + oc * 8 + kt];
                s = fmaxf(s, 0.f);
                g_h1p[((((size_t)b * 5 + oc) * 12 + oh) * 12 + ow0 + owl) * 144 + od * 12 + ot] = psh(s);
            }
            __syncthreads();
        }
    }
}

// ---------------------------------------------------------------------------
// conv2: CTA=(b, oh, ow-triple). 320 thr (10 warps). 3 ow per CTA.
// R12: B fragments read DIRECTLY from global (L2-resident; register
// software-pipeline wv/wvn) — no cp.async, no bq smem, ZERO mainloop barriers.
// SMEM (u32): xs[0,45744) | tbl @45744 (1728)  => 47472 u32 = 189888 B
// zs aliases xs after mainloop.
// ---------------------------------------------------------------------------
__global__ __launch_bounds__(320, 1)
void conv2_mma(const float* __restrict__ b2)
{
    extern __shared__ u32 sm2[];
    u32*   xs   = sm2;
    u32*   tbl  = sm2 + 45744;
    uint4* tb4  = (uint4*)tbl;
    float* zs   = (float*)sm2;            // aliases xs after mainloop

    const int bid = blockIdx.x;
    const int b = bid / 12, r0 = bid % 12;
    const int oh = r0 / 2, ow0 = (r0 % 2) * 3;
    const int tid = threadIdx.x;

    // offset table: seg' = (ic*7+kh)*9 + kw, off = seg'*144 + kd*12
    for (int i = tid; i < 1728; i += 320) {
        int kc = i >> 4, tg = (i >> 2) & 3, q = i & 3;
        int k = kc * 16 + 2 * tg + (q & 1) + (q >> 1) * 8;
        u32 off = 45360u;
        if (k < 1715) {
            int ic = k / 343, rm = k - ic * 343;
            int kh = rm / 49, rm2 = rm - kh * 49;
            int kw = rm2 / 7, kd = rm2 - kw * 7;
            off = (u32)(((ic * 7 + kh) * 9 + kw) * 144 + kd * 12);
        }
        tbl[i] = off;
    }
    for (int i = tid; i < 384; i += 320) xs[45360 + i] = 0u;
    // stage xs: 315 segs x 36 uint4
    for (int j = tid; j < 11340; j += 320) {
        int seg = j / 36, off = j % 36;
        int ic = seg / 63, r3 = seg - ic * 63;
        int kh = r3 / 9, w = r3 - kh * 9;
        *(uint4*)&xs[seg * 144 + off * 4] =
            *(const uint4*)(g_h1p + ((((size_t)b * 5 + ic) * 12 + oh + kh) * 12 + ow0 + w) * 144 + off * 4);
    }
    __syncthreads();

    const int lane = tid & 31, wid = tid >> 5, gid = lane >> 2, tig = lane & 3;
    const int mg = wid % 5, ng = wid / 5;
    const int rA = mg * 16 + gid, rB = rA + 8;

    // per-lane B base pointer: row = kc*4 + tig, col = ng*40 + nt*8 + gid
    const uint2* wbase = g_w2p + (size_t)tig * 80 + ng * 40 + gid;

    float acc[3][5][4];
#pragma unroll
    for (int e = 0; e < 3; e++)
#pragma unroll
        for (int nt = 0; nt < 5; nt++)
#pragma unroll
            for (int q = 0; q < 4; q++) acc[e][nt][q] = 0.f;

    // register-prefetched B: wv holds kc, wvn prefetches kc+1
    uint2 wv[5];
#pragma unroll
    for (int nt = 0; nt < 5; nt++) wv[nt] = __ldg(wbase + nt * 8);

#pragma unroll 4
    for (int kc = 0; kc < 108; kc++) {
        uint2 wvn[5];
        const uint2* wnext = wbase + (size_t)((kc < 107 ? kc + 1 : kc) * 4) * 80;
#pragma unroll
        for (int nt = 0; nt < 5; nt++) wvn[nt] = __ldg(wnext + nt * 8);

        const uint4 off = tb4[kc * 4 + tig];
#pragma unroll
        for (int e = 0; e < 3; e++) {
            const u32 sh = e * 144;
            u32 pa = xs[off.x + sh + rA], pb = xs[off.y + sh + rA];
            u32 pc = xs[off.x + sh + rB], pd = xs[off.y + sh + rB];
            u32 pe = xs[off.z + sh + rA], pf = xs[off.w + sh + rA];
            u32 pg = xs[off.z + sh + rB], ph = xs[off.w + sh + rB];
            u32 hh[4], ll[4];
            hh[0] = __byte_perm(pa, pb, 0x5410); ll[0] = __byte_perm(pa, pb, 0x7632);
            hh[1] = __byte_perm(pc, pd, 0x5410); ll[1] = __byte_perm(pc, pd, 0x7632);
            hh[2] = __byte_perm(pe, pf, 0x5410); ll[2] = __byte_perm(pe, pf, 0x7632);
            hh[3] = __byte_perm(pg, ph, 0x5410); ll[3] = __byte_perm(pg, ph, 0x7632);
#pragma unroll
            for (int nt = 0; nt < 5; nt++) {
                mma16816(acc[e][nt], hh, wv[nt].x, wv[nt].y);
                mma16816(acc[e][nt], ll, wv[nt].x, wv[nt].y);
            }
        }
#pragma unroll
        for (int nt = 0; nt < 5; nt++) wv[nt] = wvn[nt];
    }
    __syncthreads();   // xs reads done; zs may now overwrite

    // epilogue: zs aliases xs
#pragma unroll
    for (int e = 0; e < 3; e++) {
#pragma unroll
        for (int nt = 0; nt < 5; nt++) {
            int cb = ng * 40 + nt * 8 + 2 * tig;
            zs[rA * 82 + cb] = acc[e][nt][0];  zs[rA * 82 + cb + 1] = acc[e][nt][1];
            zs[rB * 82 + cb] = acc[e][nt][2];  zs[rB * 82 + cb + 1] = acc[e][nt][3];
        }
        __syncthreads();
        for (int i = tid; i < 360; i += 320) {
            int oc = i / 36, r2 = i - oc * 36, od = r2 / 6, ot = r2 - od * 6;
            float s = __ldg(&b2[oc]);
#pragma unroll
            for (int kt = 0; kt < 7; kt++)
                s += zs[(od * 12 + ot + kt) * 82 + oc * 8 + kt];
            s = fmaxf(s, 0.f);
            g_h2[(size_t)b * 12960 + oc * 1296 + oh * 216 + (ow0 + e) * 36 + od * 6 + ot] = s;
        }
        __syncthreads();
    }
}

// ---------------------------------------------------------------------------
__global__ __launch_bounds__(256)
void linear_kernel(const float* __restrict__ wl, const float* __restrict__ bl,
                   float* __restrict__ out)
{
    const int b = blockIdx.x;
    const float* h = g_h2 + (size_t)b * 12960;
    float s = 0.f;
    for (int i = threadIdx.x; i < 12960; i += 256) s = fmaf(h[i], wl[i], s);
    __shared__ float red[8];
#pragma unroll
    for (int o = 16; o; o >>= 1) s += __shfl_xor_sync(0xFFFFFFFFu, s, o);
    if ((threadIdx.x & 31) == 0) red[threadIdx.x >> 5] = s;
    __syncthreads();
    if (threadIdx.x < 32) {
        s = (threadIdx.x < 8) ? red[threadIdx.x] : 0.f;
#pragma unroll
        for (int o = 4; o; o >>= 1) s += __shfl_xor_sync(0xFFFFFFFFu, s, o);
        if (threadIdx.x == 0) out[b] = 1.f / (1.f + expf(-(s + bl[0])));
    }
}

// ---------------------------------------------------------------------------
extern "C" void kernel_launch(void* const* d_in, const int* in_sizes, int n_in,
                              void* d_out, int out_size)
{
    const float* x    = (const float*)d_in[0];
    const float* w1   = (const float*)d_in[1];
    const float* b1   = (const float*)d_in[2];
    const float* w2   = (const float*)d_in[3];
    const float* b2   = (const float*)d_in[4];
    const float* wlin = (const float*)d_in[5];
    const float* blin = (const float*)d_in[6];
    float* out = (float*)d_out;

    const size_t smem1 = 46224u * 4;   // 184896 B
    const size_t smem2 = 47472u * 4;   // 189888 B
    cudaFuncSetAttribute(conv1_mma, cudaFuncAttributeMaxDynamicSharedMemorySize, (int)smem1);
    cudaFuncSetAttribute(conv2_mma, cudaFuncAttributeMaxDynamicSharedMemorySize, (int)smem2);

    pack_x<<<(NB * 104976 + 255) / 256, 256>>>(x);
    pack_w1<<<14, 256>>>(w1);
    pack_w2<<<135, 256>>>(w2);
    conv1_mma<<<NB * 24, 448, smem1>>>(b1);
    conv2_mma<<<NB * 12, 320, smem2>>>(b2);
    linear_kernel<<<NB, 256>>>(wlin, blin, out);
}

// round 16
// speedup vs baseline: 2.1379x; 1.0162x over previous
#include <cuda_runtime.h>
#include <cuda_fp16.h>
typedef unsigned int u32;
#define NB 128

// ---------------------------------------------------------------------------
// Globals (no cudaMalloc allowed)
// ---------------------------------------------------------------------------
__device__ __align__(16) u32   g_xp[NB * 18 * 18 * 324];          // x split-packed fp16, dense [h][w][d][t]
__device__ __align__(16) u32   g_h1p[NB * 5 * 12 * 12 * 144];     // conv1 out split-packed fp16
__device__ float               g_h2[NB * 10 * 1296];
__device__ __align__(16) uint2 g_w1p[22 * 4 * 40];                // B1 fp16 fragments
__device__ __align__(16) uint2 g_w2p[108 * 4 * 80];               // B2 fp16 fragments

// ---------------------------------------------------------------------------
__device__ __forceinline__ u32 psh(float v) {   // split-pack: fp16 hi | fp16 lo<<16
    __half h = __float2half_rn(v);
    __half l = __float2half_rn(v - __half2float(h));
    return (u32)__half_as_ushort(h) | ((u32)__half_as_ushort(l) << 16);
}
__device__ __forceinline__ u32 ph2(float v0, float v1) {
    return (u32)__half_as_ushort(__float2half_rn(v0))
         | ((u32)__half_as_ushort(__float2half_rn(v1)) << 16);
}
__device__ __forceinline__ void mma16816(float* c, const u32* a, u32 b0, u32 b1) {
    asm volatile("mma.sync.aligned.m16n8k16.row.col.f32.f16.f16.f32 "
        "{%0,%1,%2,%3},{%4,%5,%6,%7},{%8,%9},{%0,%1,%2,%3};"
        : "+f"(c[0]), "+f"(c[1]), "+f"(c[2]), "+f"(c[3])
        : "r"(a[0]), "r"(a[1]), "r"(a[2]), "r"(a[3]), "r"(b0), "r"(b1));
}

// ---------------------------------------------------------------------------
// pack kernels
// ---------------------------------------------------------------------------
__global__ void pack_x(const float* __restrict__ x) {
    int i = blockIdx.x * 256 + threadIdx.x;
    if (i >= NB * 104976) return;
    g_xp[i] = psh(x[i]);
}
__global__ void pack_w1(const float* __restrict__ w1) {
    int i = blockIdx.x * 256 + threadIdx.x;
    if (i >= 3520) return;
    int kcti = i / 40, n = i % 40, oc = n >> 3, kt = n & 7;
    int k0 = (kcti >> 2) * 16 + 2 * (kcti & 3);
    float v[4];
#pragma unroll
    for (int j = 0; j < 4; j++) {
        int k = k0 + (j & 1) + (j >> 1) * 8;
        v[j] = (k < 343 && kt < 7) ? w1[oc * 2401 + k * 7 + kt] : 0.f;
    }
    uint2 o; o.x = ph2(v[0], v[1]); o.y = ph2(v[2], v[3]);
    g_w1p[i] = o;
}
__global__ void pack_w2(const float* __restrict__ w2) {
    int i = blockIdx.x * 256 + threadIdx.x;
    if (i >= 34560) return;
    int kcti = i / 80, n = i % 80, oc = n >> 3, kt = n & 7;
    int k0 = (kcti >> 2) * 16 + 2 * (kcti & 3);
    float v[4];
#pragma unroll
    for (int j = 0; j < 4; j++) {
        int k = k0 + (j & 1) + (j >> 1) * 8;
        v[j] = 0.f;
        if (k < 1715 && kt < 7) {
            int ic = k / 343, t3 = k - ic * 343;
            v[j] = w2[(size_t)oc * 12005 + ic * 2401 + t3 * 7 + kt];
        }
    }
    uint2 o; o.x = ph2(v[0], v[1]); o.y = ph2(v[2], v[3]);
    g_w2p[i] = o;
}

// ---------------------------------------------------------------------------
// conv1: CTA=(b, oh, ow-half). 448 thr (14 warps, 1 m-tile each).
// Dense stride-18, 2 passes x 3 owl. (unchanged from R12/R13 winner)
// SMEM (u32): xs[0,29072) | tbl @29072 (352) | ws2 @29424 (7392) | zs @36816 (9408)
// ---------------------------------------------------------------------------
__global__ __launch_bounds__(448, 1)
void conv1_mma(const float* __restrict__ b1)
{
    extern __shared__ u32 sm[];
    u32*   xs   = sm;
    u32*   tbl  = sm + 29072;
    uint4* tb4  = (uint4*)tbl;
    uint2* ws2  = (uint2*)(sm + 29424);
    float* zs   = (float*)(sm + 36816);

    const int bid = blockIdx.x;
    const int b = bid / 24, r0 = bid % 24, oh = r0 >> 1, ow0 = (r0 & 1) * 6;
    const int tid = threadIdx.x;

    if (tid < 352) {
        int kc = tid >> 4, tg = (tid >> 2) & 3, q = tid & 3;
        int k = kc * 16 + 2 * tg + (q & 1) + (q >> 1) * 8;
        u32 off = 27216u;
        if (k < 343) {
            int kh = k / 49, rm = k - kh * 49, kw = rm / 7, kd = rm - kw * 7;
            off = (u32)((kh * 12 + kw) * 324 + kd * 18);
        }
        tbl[tid] = off;
    }
    for (int i = tid; i < 3520; i += 448) ws2[(i / 40) * 42 + i % 40] = g_w1p[i];
    for (int i = tid; i < 1856; i += 448) xs[27216 + i] = 0u;
    const u32* xb = g_xp + (((size_t)b * 18 + oh) * 18 + ow0) * 324;
    for (int j = tid; j < 6804; j += 448) {
        int seg = j / 81, off = j % 81;
        *(uint4*)&xs[seg * 324 + off * 4] =
            *(const uint4*)(xb + ((size_t)(seg / 12) * 18 + seg % 12) * 324 + off * 4);
    }
    __syncthreads();

    const int lane = tid & 31, wid = tid >> 5, gid = lane >> 2, tig = lane & 3;
    const int rA = wid * 16 + gid;

    for (int p = 0; p < 2; p++) {
        const int bA = p * 972 + rA;             // owl0 = 3p
        float acc[3][5][4];
#pragma unroll
        for (int e = 0; e < 3; e++)
#pragma unroll
            for (int nt = 0; nt < 5; nt++)
#pragma unroll
                for (int q = 0; q < 4; q++) acc[e][nt][q] = 0.f;

#pragma unroll
        for (int kc = 0; kc < 22; kc++) {
            const uint4 off = tb4[kc * 4 + tig];
            uint2 wv[5];
#pragma unroll
            for (int nt = 0; nt < 5; nt++)
                wv[nt] = ws2[(kc * 4 + tig) * 42 + nt * 8 + gid];
#pragma unroll
            for (int e = 0; e < 3; e++) {
                const u32 sh = e * 324 + bA;
                u32 pa = xs[off.x + sh],     pb = xs[off.y + sh];
                u32 pc = xs[off.x + sh + 8], pd = xs[off.y + sh + 8];
                u32 pe = xs[off.z + sh],     pf = xs[off.w + sh];
                u32 pg = xs[off.z + sh + 8], ph = xs[off.w + sh + 8];
                u32 hh[4], ll[4];
                hh[0] = __byte_perm(pa, pb, 0x5410); ll[0] = __byte_perm(pa, pb, 0x7632);
                hh[1] = __byte_perm(pc, pd, 0x5410); ll[1] = __byte_perm(pc, pd, 0x7632);
                hh[2] = __byte_perm(pe, pf, 0x5410); ll[2] = __byte_perm(pe, pf, 0x7632);
                hh[3] = __byte_perm(pg, ph, 0x5410); ll[3] = __byte_perm(pg, ph, 0x7632);
#pragma unroll
                for (int nt = 0; nt < 5; nt++) {
                    mma16816(acc[e][nt], hh, wv[nt].x, wv[nt].y);
                    mma16816(acc[e][nt], ll, wv[nt].x, wv[nt].y);
                }
            }
        }

#pragma unroll
        for (int e = 0; e < 3; e++) {
            const int owl = 3 * p + e;
#pragma unroll
            for (int nt = 0; nt < 5; nt++) {
                int cb = nt * 8 + 2 * tig;
                zs[rA * 42 + cb]       = acc[e][nt][0];  zs[rA * 42 + cb + 1]       = acc[e][nt][1];
                zs[(rA + 8) * 42 + cb] = acc[e][nt][2];  zs[(rA + 8) * 42 + cb + 1] = acc[e][nt][3];
            }
            __syncthreads();
            for (int i = tid; i < 720; i += 448) {
                int oc = i / 144, r2 = i - oc * 144, od = r2 / 12, ot = r2 - od * 12;
                float s = __ldg(&b1[oc]);
#pragma unroll
                for (int kt = 0; kt < 7; kt++)
                    s += zs[(od * 18 + ot + kt) * 42 + oc * 8 + kt];
                s = fmaxf(s, 0.f);
                g_h1p[((((size_t)b * 5 + oc) * 12 + oh) * 12 + ow0 + owl) * 144 + od * 12 + ot] = psh(s);
            }
            __syncthreads();
        }
    }
}

// ---------------------------------------------------------------------------
// conv2: CTA=(b, oh, ow-triple). 640 thr (20 warps): 2-way K-SPLIT.
// Warps 0-9: kc 0..53; warps 10-19: kc 54..107. Partials summed via two zs
// regions (aliasing dead xs). B read directly from global (L2-resident).
// SMEM (u32): xs[0,45744) | tbl @45744 (1728)  => 47472 u32 = 189888 B
// zs0 @0 (6560 f32), zs1 @6560 (6560 f32) — both alias xs after mainloop.
// ---------------------------------------------------------------------------
__global__ __launch_bounds__(640, 1)
void conv2_mma(const float* __restrict__ b2)
{
    extern __shared__ u32 sm2[];
    u32*   xs   = sm2;
    u32*   tbl  = sm2 + 45744;
    uint4* tb4  = (uint4*)tbl;
    float* zs0  = (float*)sm2;            // aliases xs after mainloop
    float* zs1  = zs0 + 6560;

    const int bid = blockIdx.x;
    const int b = bid / 12, r0 = bid % 12;
    const int oh = r0 / 2, ow0 = (r0 % 2) * 3;
    const int tid = threadIdx.x;

    // offset table: seg' = (ic*7+kh)*9 + kw, off = seg'*144 + kd*12
    for (int i = tid; i < 1728; i += 640) {
        int kc = i >> 4, tg = (i >> 2) & 3, q = i & 3;
        int k = kc * 16 + 2 * tg + (q & 1) + (q >> 1) * 8;
        u32 off = 45360u;
        if (k < 1715) {
            int ic = k / 343, rm = k - ic * 343;
            int kh = rm / 49, rm2 = rm - kh * 49;
            int kw = rm2 / 7, kd = rm2 - kw * 7;
            off = (u32)(((ic * 7 + kh) * 9 + kw) * 144 + kd * 12);
        }
        tbl[i] = off;
    }
    for (int i = tid; i < 384; i += 640) xs[45360 + i] = 0u;
    // stage xs: 315 segs x 36 uint4
    for (int j = tid; j < 11340; j += 640) {
        int seg = j / 36, off = j % 36;
        int ic = seg / 63, r3 = seg - ic * 63;
        int kh = r3 / 9, w = r3 - kh * 9;
        *(uint4*)&xs[seg * 144 + off * 4] =
            *(const uint4*)(g_h1p + ((((size_t)b * 5 + ic) * 12 + oh + kh) * 12 + ow0 + w) * 144 + off * 4);
    }
    __syncthreads();

    const int lane = tid & 31, wid = tid >> 5, gid = lane >> 2, tig = lane & 3;
    const int khalf = wid / 10;           // 0: kc 0..53, 1: kc 54..107
    const int w10 = wid - khalf * 10;
    const int mg = w10 % 5, ng = w10 / 5;
    const int rA = mg * 16 + gid, rB = rA + 8;

    // per-lane B base pointer: row = kc*4 + tig, col = ng*40 + nt*8 + gid
    const uint2* wbase = g_w2p + (size_t)(khalf * 54 * 4 + tig) * 80 + ng * 40 + gid;
    const uint4* tbase = tb4 + khalf * 54 * 4 + tig;

    float acc[3][5][4];
#pragma unroll
    for (int e = 0; e < 3; e++)
#pragma unroll
        for (int nt = 0; nt < 5; nt++)
#pragma unroll
            for (int q = 0; q < 4; q++) acc[e][nt][q] = 0.f;

#pragma unroll 2
    for (int kc = 0; kc < 54; kc++) {
        uint2 wv[5];
        const uint2* wrow = wbase + (size_t)(kc * 4) * 80;
#pragma unroll
        for (int nt = 0; nt < 5; nt++) wv[nt] = __ldg(wrow + nt * 8);

        const uint4 off = tbase[kc * 4];
#pragma unroll
        for (int e = 0; e < 3; e++) {
            const u32 sh = e * 144;
            u32 pa = xs[off.x + sh + rA], pb = xs[off.y + sh + rA];
            u32 pc = xs[off.x + sh + rB], pd = xs[off.y + sh + rB];
            u32 pe = xs[off.z + sh + rA], pf = xs[off.w + sh + rA];
            u32 pg = xs[off.z + sh + rB], ph = xs[off.w + sh + rB];
            u32 hh[4], ll[4];
            hh[0] = __byte_perm(pa, pb, 0x5410); ll[0] = __byte_perm(pa, pb, 0x7632);
            hh[1] = __byte_perm(pc, pd, 0x5410); ll[1] = __byte_perm(pc, pd, 0x7632);
            hh[2] = __byte_perm(pe, pf, 0x5410); ll[2] = __byte_perm(pe, pf, 0x7632);
            hh[3] = __byte_perm(pg, ph, 0x5410); ll[3] = __byte_perm(pg, ph, 0x7632);
#pragma unroll
            for (int nt = 0; nt < 5; nt++) {
                mma16816(acc[e][nt], hh, wv[nt].x, wv[nt].y);
                mma16816(acc[e][nt], ll, wv[nt].x, wv[nt].y);
            }
        }
    }
    __syncthreads();   // xs reads done; zs0/zs1 may now overwrite

    // epilogue: each K-half writes its own zs region; outputs sum both.
    float* zsw = khalf ? zs1 : zs0;
#pragma unroll
    for (int e = 0; e < 3; e++) {
#pragma unroll
        for (int nt = 0; nt < 5; nt++) {
            int cb = ng * 40 + nt * 8 + 2 * tig;
            zsw[rA * 82 + cb] = acc[e][nt][0];  zsw[rA * 82 + cb + 1] = acc[e][nt][1];
            zsw[rB * 82 + cb] = acc[e][nt][2];  zsw[rB * 82 + cb + 1] = acc[e][nt][3];
        }
        __syncthreads();
        for (int i = tid; i < 360; i += 640) {
            int oc = i / 36, r2 = i - oc * 36, od = r2 / 6, ot = r2 - od * 6;
            float s = __ldg(&b2[oc]);
#pragma unroll
            for (int kt = 0; kt < 7; kt++) {
                int zi = (od * 12 + ot + kt) * 82 + oc * 8 + kt;
                s += zs0[zi] + zs1[zi];
            }
            s = fmaxf(s, 0.f);
            g_h2[(size_t)b * 12960 + oc * 1296 + oh * 216 + (ow0 + e) * 36 + od * 6 + ot] = s;
        }
        __syncthreads();
    }
}

// ---------------------------------------------------------------------------
__global__ __launch_bounds__(256)
void linear_kernel(const float* __restrict__ wl, const float* __restrict__ bl,
                   float* __restrict__ out)
{
    const int b = blockIdx.x;
    const float* h = g_h2 + (size_t)b * 12960;
    float s = 0.f;
    for (int i = threadIdx.x; i < 12960; i += 256) s = fmaf(h[i], wl[i], s);
    __shared__ float red[8];
#pragma unroll
    for (int o = 16; o; o >>= 1) s += __shfl_xor_sync(0xFFFFFFFFu, s, o);
    if ((threadIdx.x & 31) == 0) red[threadIdx.x >> 5] = s;
    __syncthreads();
    if (threadIdx.x < 32) {
        s = (threadIdx.x < 8) ? red[threadIdx.x] : 0.f;
#pragma unroll
        for (int o = 4; o; o >>= 1) s += __shfl_xor_sync(0xFFFFFFFFu, s, o);
        if (threadIdx.x == 0) out[b] = 1.f / (1.f + expf(-(s + bl[0])));
    }
}

// ---------------------------------------------------------------------------
extern "C" void kernel_launch(void* const* d_in, const int* in_sizes, int n_in,
                              void* d_out, int out_size)
{
    const float* x    = (const float*)d_in[0];
    const float* w1   = (const float*)d_in[1];
    const float* b1   = (const float*)d_in[2];
    const float* w2   = (const float*)d_in[3];
    const float* b2   = (const float*)d_in[4];
    const float* wlin = (const float*)d_in[5];
    const float* blin = (const float*)d_in[6];
    float* out = (float*)d_out;

    const size_t smem1 = 46224u * 4;   // 184896 B
    const size_t smem2 = 47472u * 4;   // 189888 B
    cudaFuncSetAttribute(conv1_mma, cudaFuncAttributeMaxDynamicSharedMemorySize, (int)smem1);
    cudaFuncSetAttribute(conv2_mma, cudaFuncAttributeMaxDynamicSharedMemorySize, (int)smem2);

    pack_x<<<(NB * 104976 + 255) / 256, 256>>>(x);
    pack_w1<<<14, 256>>>(w1);
    pack_w2<<<135, 256>>>(w2);
    conv1_mma<<<NB * 24, 448, smem1>>>(b1);
    conv2_mma<<<NB * 12, 640, smem2>>>(b2);
    linear_kernel<<<NB, 256>>>(wlin, blin, out);
}

// round 17
// speedup vs baseline: 2.3236x; 1.0869x over previous
#include <cuda_runtime.h>
#include <cuda_fp16.h>
typedef unsigned int u32;
#define NB 128

// ---------------------------------------------------------------------------
// Globals (no cudaMalloc allowed)
// ---------------------------------------------------------------------------
__device__ __align__(16) u32   g_xp[NB * 18 * 18 * 324];          // x split-packed fp16, dense [h][w][d][t]
__device__ __align__(16) u32   g_h1p[NB * 5 * 12 * 12 * 144];     // conv1 out split-packed fp16
__device__ float               g_h2[NB * 10 * 1296];
__device__ __align__(16) uint2 g_w1p[22 * 4 * 40];                // B1 fp16 fragments (N=40)
__device__ __align__(16) uint2 g_w2p[108 * 4 * 72];               // B2 fp16 fragments (N=72, n=oc*7+kt)

// ---------------------------------------------------------------------------
__device__ __forceinline__ u32 psh(float v) {   // split-pack: fp16 hi | fp16 lo<<16
    __half h = __float2half_rn(v);
    __half l = __float2half_rn(v - __half2float(h));
    return (u32)__half_as_ushort(h) | ((u32)__half_as_ushort(l) << 16);
}
__device__ __forceinline__ u32 ph2(float v0, float v1) {
    return (u32)__half_as_ushort(__float2half_rn(v0))
         | ((u32)__half_as_ushort(__float2half_rn(v1)) << 16);
}
__device__ __forceinline__ void mma16816(float* c, const u32* a, u32 b0, u32 b1) {
    asm volatile("mma.sync.aligned.m16n8k16.row.col.f32.f16.f16.f32 "
        "{%0,%1,%2,%3},{%4,%5,%6,%7},{%8,%9},{%0,%1,%2,%3};"
        : "+f"(c[0]), "+f"(c[1]), "+f"(c[2]), "+f"(c[3])
        : "r"(a[0]), "r"(a[1]), "r"(a[2]), "r"(a[3]), "r"(b0), "r"(b1));
}

// ---------------------------------------------------------------------------
// pack kernels
// ---------------------------------------------------------------------------
__global__ void pack_x(const float* __restrict__ x) {
    int i = blockIdx.x * 256 + threadIdx.x;
    if (i >= NB * 104976) return;
    g_xp[i] = psh(x[i]);
}
__global__ void pack_w1(const float* __restrict__ w1) {
    int i = blockIdx.x * 256 + threadIdx.x;
    if (i >= 3520) return;
    int kcti = i / 40, n = i % 40, oc = n >> 3, kt = n & 7;
    int k0 = (kcti >> 2) * 16 + 2 * (kcti & 3);
    float v[4];
#pragma unroll
    for (int j = 0; j < 4; j++) {
        int k = k0 + (j & 1) + (j >> 1) * 8;
        v[j] = (k < 343 && kt < 7) ? w1[oc * 2401 + k * 7 + kt] : 0.f;
    }
    uint2 o; o.x = ph2(v[0], v[1]); o.y = ph2(v[2], v[3]);
    g_w1p[i] = o;
}
// N=72 mapping: n = oc*7 + kt (valid n<70; 70,71 zero pad)
__global__ void pack_w2(const float* __restrict__ w2) {
    int i = blockIdx.x * 256 + threadIdx.x;
    if (i >= 108 * 4 * 72) return;
    int kcti = i / 72, n = i % 72;
    int oc = n / 7, kt = n - oc * 7;        // oc<=10 when n>=70 -> invalid
    int k0 = (kcti >> 2) * 16 + 2 * (kcti & 3);
    float v[4];
#pragma unroll
    for (int j = 0; j < 4; j++) {
        int k = k0 + (j & 1) + (j >> 1) * 8;
        v[j] = 0.f;
        if (k < 1715 && n < 70) {
            int ic = k / 343, t3 = k - ic * 343;
            v[j] = w2[(size_t)oc * 12005 + ic * 2401 + t3 * 7 + kt];
        }
    }
    uint2 o; o.x = ph2(v[0], v[1]); o.y = ph2(v[2], v[3]);
    g_w2p[i] = o;
}

// ---------------------------------------------------------------------------
// conv1: CTA=(b, oh, ow-half). 448 thr (14 warps, 1 m-tile each).
// Dense stride-18, 2 passes x 3 owl. (unchanged)
// SMEM (u32): xs[0,29072) | tbl @29072 (352) | ws2 @29424 (7392) | zs @36816 (9408)
// ---------------------------------------------------------------------------
__global__ __launch_bounds__(448, 1)
void conv1_mma(const float* __restrict__ b1)
{
    extern __shared__ u32 sm[];
    u32*   xs   = sm;
    u32*   tbl  = sm + 29072;
    uint4* tb4  = (uint4*)tbl;
    uint2* ws2  = (uint2*)(sm + 29424);
    float* zs   = (float*)(sm + 36816);

    const int bid = blockIdx.x;
    const int b = bid / 24, r0 = bid % 24, oh = r0 >> 1, ow0 = (r0 & 1) * 6;
    const int tid = threadIdx.x;

    if (tid < 352) {
        int kc = tid >> 4, tg = (tid >> 2) & 3, q = tid & 3;
        int k = kc * 16 + 2 * tg + (q & 1) + (q >> 1) * 8;
        u32 off = 27216u;
        if (k < 343) {
            int kh = k / 49, rm = k - kh * 49, kw = rm / 7, kd = rm - kw * 7;
            off = (u32)((kh * 12 + kw) * 324 + kd * 18);
        }
        tbl[tid] = off;
    }
    for (int i = tid; i < 3520; i += 448) ws2[(i / 40) * 42 + i % 40] = g_w1p[i];
    for (int i = tid; i < 1856; i += 448) xs[27216 + i] = 0u;
    const u32* xb = g_xp + (((size_t)b * 18 + oh) * 18 + ow0) * 324;
    for (int j = tid; j < 6804; j += 448) {
        int seg = j / 81, off = j % 81;
        *(uint4*)&xs[seg * 324 + off * 4] =
            *(const uint4*)(xb + ((size_t)(seg / 12) * 18 + seg % 12) * 324 + off * 4);
    }
    __syncthreads();

    const int lane = tid & 31, wid = tid >> 5, gid = lane >> 2, tig = lane & 3;
    const int rA = wid * 16 + gid;

    for (int p = 0; p < 2; p++) {
        const int bA = p * 972 + rA;             // owl0 = 3p
        float acc[3][5][4];
#pragma unroll
        for (int e = 0; e < 3; e++)
#pragma unroll
            for (int nt = 0; nt < 5; nt++)
#pragma unroll
                for (int q = 0; q < 4; q++) acc[e][nt][q] = 0.f;

#pragma unroll
        for (int kc = 0; kc < 22; kc++) {
            const uint4 off = tb4[kc * 4 + tig];
            uint2 wv[5];
#pragma unroll
            for (int nt = 0; nt < 5; nt++)
                wv[nt] = ws2[(kc * 4 + tig) * 42 + nt * 8 + gid];
#pragma unroll
            for (int e = 0; e < 3; e++) {
                const u32 sh = e * 324 + bA;
                u32 pa = xs[off.x + sh],     pb = xs[off.y + sh];
                u32 pc = xs[off.x + sh + 8], pd = xs[off.y + sh + 8];
                u32 pe = xs[off.z + sh],     pf = xs[off.w + sh];
                u32 pg = xs[off.z + sh + 8], ph = xs[off.w + sh + 8];
                u32 hh[4], ll[4];
                hh[0] = __byte_perm(pa, pb, 0x5410); ll[0] = __byte_perm(pa, pb, 0x7632);
                hh[1] = __byte_perm(pc, pd, 0x5410); ll[1] = __byte_perm(pc, pd, 0x7632);
                hh[2] = __byte_perm(pe, pf, 0x5410); ll[2] = __byte_perm(pe, pf, 0x7632);
                hh[3] = __byte_perm(pg, ph, 0x5410); ll[3] = __byte_perm(pg, ph, 0x7632);
#pragma unroll
                for (int nt = 0; nt < 5; nt++) {
                    mma16816(acc[e][nt], hh, wv[nt].x, wv[nt].y);
                    mma16816(acc[e][nt], ll, wv[nt].x, wv[nt].y);
                }
            }
        }

#pragma unroll
        for (int e = 0; e < 3; e++) {
            const int owl = 3 * p + e;
#pragma unroll
            for (int nt = 0; nt < 5; nt++) {
                int cb = nt * 8 + 2 * tig;
                zs[rA * 42 + cb]       = acc[e][nt][0];  zs[rA * 42 + cb + 1]       = acc[e][nt][1];
                zs[(rA + 8) * 42 + cb] = acc[e][nt][2];  zs[(rA + 8) * 42 + cb + 1] = acc[e][nt][3];
            }
            __syncthreads();
            for (int i = tid; i < 720; i += 448) {
                int oc = i / 144, r2 = i - oc * 144, od = r2 / 12, ot = r2 - od * 12;
                float s = __ldg(&b1[oc]);
#pragma unroll
                for (int kt = 0; kt < 7; kt++)
                    s += zs[(od * 18 + ot + kt) * 42 + oc * 8 + kt];
                s = fmaxf(s, 0.f);
                g_h1p[((((size_t)b * 5 + oc) * 12 + oh) * 12 + ow0 + owl) * 144 + od * 12 + ot] = psh(s);
            }
            __syncthreads();
        }
    }
}

// ---------------------------------------------------------------------------
// conv2: CTA=(b, oh, ow-triple). 640 thr (20 warps): 2-way K-SPLIT, N=72.
// ng0 warps: n-tiles 0..4 (cols 0..39); ng1 warps: n-tiles 5..8 (cols 40..71).
// Partials in two zs regions (row stride 74) aliasing dead xs; B direct from L2.
// SMEM (u32): xs[0,45744) | tbl @45744 (1728)  => 47472 u32 = 189888 B
// ---------------------------------------------------------------------------
__global__ __launch_bounds__(640, 1)
void conv2_mma(const float* __restrict__ b2)
{
    extern __shared__ u32 sm2[];
    u32*   xs   = sm2;
    u32*   tbl  = sm2 + 45744;
    uint4* tb4  = (uint4*)tbl;
    float* zs0  = (float*)sm2;            // aliases xs after mainloop (80*74 f32)
    float* zs1  = zs0 + 5920;

    const int bid = blockIdx.x;
    const int b = bid / 12, r0 = bid % 12;
    const int oh = r0 / 2, ow0 = (r0 % 2) * 3;
    const int tid = threadIdx.x;

    // offset table: seg' = (ic*7+kh)*9 + kw, off = seg'*144 + kd*12
    for (int i = tid; i < 1728; i += 640) {
        int kc = i >> 4, tg = (i >> 2) & 3, q = i & 3;
        int k = kc * 16 + 2 * tg + (q & 1) + (q >> 1) * 8;
        u32 off = 45360u;
        if (k < 1715) {
            int ic = k / 343, rm = k - ic * 343;
            int kh = rm / 49, rm2 = rm - kh * 49;
            int kw = rm2 / 7, kd = rm2 - kw * 7;
            off = (u32)(((ic * 7 + kh) * 9 + kw) * 144 + kd * 12);
        }
        tbl[i] = off;
    }
    for (int i = tid; i < 384; i += 640) xs[45360 + i] = 0u;
    // stage xs: 315 segs x 36 uint4
    for (int j = tid; j < 11340; j += 640) {
        int seg = j / 36, off = j % 36;
        int ic = seg / 63, r3 = seg - ic * 63;
        int kh = r3 / 9, w = r3 - kh * 9;
        *(uint4*)&xs[seg * 144 + off * 4] =
            *(const uint4*)(g_h1p + ((((size_t)b * 5 + ic) * 12 + oh + kh) * 12 + ow0 + w) * 144 + off * 4);
    }
    __syncthreads();

    const int lane = tid & 31, wid = tid >> 5, gid = lane >> 2, tig = lane & 3;
    const int khalf = wid / 10;           // 0: kc 0..53, 1: kc 54..107
    const int w10 = wid - khalf * 10;
    const int mg = w10 % 5, ng = w10 / 5;
    const int ntn = 5 - ng;               // ng0: 5 n-tiles, ng1: 4 n-tiles
    const int rA = mg * 16 + gid, rB = rA + 8;

    // per-lane B base pointer: row = kc*4 + tig, col = ng*40 + nt*8 + gid
    const uint2* wbase = g_w2p + (size_t)(khalf * 54 * 4 + tig) * 72 + ng * 40 + gid;
    const uint4* tbase = tb4 + khalf * 54 * 4 + tig;

    float acc[3][5][4];
#pragma unroll
    for (int e = 0; e < 3; e++)
#pragma unroll
        for (int nt = 0; nt < 5; nt++)
#pragma unroll
            for (int q = 0; q < 4; q++) acc[e][nt][q] = 0.f;

#pragma unroll 2
    for (int kc = 0; kc < 54; kc++) {
        uint2 wv[5];
        const uint2* wrow = wbase + (size_t)(kc * 4) * 72;
#pragma unroll
        for (int nt = 0; nt < 5; nt++)
            if (nt < ntn) wv[nt] = __ldg(wrow + nt * 8);

        const uint4 off = tbase[kc * 4];
#pragma unroll
        for (int e = 0; e < 3; e++) {
            const u32 sh = e * 144;
            u32 pa = xs[off.x + sh + rA], pb = xs[off.y + sh + rA];
            u32 pc = xs[off.x + sh + rB], pd = xs[off.y + sh + rB];
            u32 pe = xs[off.z + sh + rA], pf = xs[off.w + sh + rA];
            u32 pg = xs[off.z + sh + rB], ph = xs[off.w + sh + rB];
            u32 hh[4], ll[4];
            hh[0] = __byte_perm(pa, pb, 0x5410); ll[0] = __byte_perm(pa, pb, 0x7632);
            hh[1] = __byte_perm(pc, pd, 0x5410); ll[1] = __byte_perm(pc, pd, 0x7632);
            hh[2] = __byte_perm(pe, pf, 0x5410); ll[2] = __byte_perm(pe, pf, 0x7632);
            hh[3] = __byte_perm(pg, ph, 0x5410); ll[3] = __byte_perm(pg, ph, 0x7632);
#pragma unroll
            for (int nt = 0; nt < 5; nt++) {
                if (nt < ntn) {
                    mma16816(acc[e][nt], hh, wv[nt].x, wv[nt].y);
                    mma16816(acc[e][nt], ll, wv[nt].x, wv[nt].y);
                }
            }
        }
    }
    __syncthreads();   // xs reads done; zs0/zs1 may now overwrite

    // epilogue: each K-half writes its own zs region; outputs sum both.
    float* zsw = khalf ? zs1 : zs0;
#pragma unroll
    for (int e = 0; e < 3; e++) {
#pragma unroll
        for (int nt = 0; nt < 5; nt++) {
            if (nt < ntn) {
                int cb = ng * 40 + nt * 8 + 2 * tig;
                zsw[rA * 74 + cb] = acc[e][nt][0];  zsw[rA * 74 + cb + 1] = acc[e][nt][1];
                zsw[rB * 74 + cb] = acc[e][nt][2];  zsw[rB * 74 + cb + 1] = acc[e][nt][3];
            }
        }
        __syncthreads();
        for (int i = tid; i < 360; i += 640) {
            int oc = i / 36, r2 = i - oc * 36, od = r2 / 6, ot = r2 - od * 6;
            float s = __ldg(&b2[oc]);
#pragma unroll
            for (int kt = 0; kt < 7; kt++) {
                int zi = (od * 12 + ot + kt) * 74 + oc * 7 + kt;
                s += zs0[zi] + zs1[zi];
            }
            s = fmaxf(s, 0.f);
            g_h2[(size_t)b * 12960 + oc * 1296 + oh * 216 + (ow0 + e) * 36 + od * 6 + ot] = s;
        }
        __syncthreads();
    }
}

// ---------------------------------------------------------------------------
__global__ __launch_bounds__(256)
void linear_kernel(const float* __restrict__ wl, const float* __restrict__ bl,
                   float* __restrict__ out)
{
    const int b = blockIdx.x;
    const float* h = g_h2 + (size_t)b * 12960;
    float s = 0.f;
    for (int i = threadIdx.x; i < 12960; i += 256) s = fmaf(h[i], wl[i], s);
    __shared__ float red[8];
#pragma unroll
    for (int o = 16; o; o >>= 1) s += __shfl_xor_sync(0xFFFFFFFFu, s, o);
    if ((threadIdx.x & 31) == 0) red[threadIdx.x >> 5] = s;
    __syncthreads();
    if (threadIdx.x < 32) {
        s = (threadIdx.x < 8) ? red[threadIdx.x] : 0.f;
#pragma unroll
        for (int o = 4; o; o >>= 1) s += __shfl_xor_sync(0xFFFFFFFFu, s, o);
        if (threadIdx.x == 0) out[b] = 1.f / (1.f + expf(-(s + bl[0])));
    }
}

// ---------------------------------------------------------------------------
extern "C" void kernel_launch(void* const* d_in, const int* in_sizes, int n_in,
                              void* d_out, int out_size)
{
    const float* x    = (const float*)d_in[0];
    const float* w1   = (const float*)d_in[1];
    const float* b1   = (const float*)d_in[2];
    const float* w2   = (const float*)d_in[3];
    const float* b2   = (const float*)d_in[4];
    const float* wlin = (const float*)d_in[5];
    const float* blin = (const float*)d_in[6];
    float* out = (float*)d_out;

    const size_t smem1 = 46224u * 4;   // 184896 B
    const size_t smem2 = 47472u * 4;   // 189888 B
    cudaFuncSetAttribute(conv1_mma, cudaFuncAttributeMaxDynamicSharedMemorySize, (int)smem1);
    cudaFuncSetAttribute(conv2_mma, cudaFuncAttributeMaxDynamicSharedMemorySize, (int)smem2);

    pack_x<<<(NB * 104976 + 255) / 256, 256>>>(x);
    pack_w1<<<14, 256>>>(w1);
    pack_w2<<<(108 * 4 * 72 + 255) / 256, 256>>>(w2);
    conv1_mma<<<NB * 24, 448, smem1>>>(b1);
    conv2_mma<<<NB * 12, 640, smem2>>>(b2);
    linear_kernel<<<NB, 256>>>(wlin, blin, out);
}